// round 1
// baseline (speedup 1.0000x reference)
#include <cuda_runtime.h>

#define BB    32
#define NN    96
#define DD    64
#define LL    5
#define NPAIR 9216            // N*N
#define PTOT  294912          // B*N*N
#define BEP   24576           // B*EP
#define EV    5

// ---- scratch (device globals; no allocation allowed) ----
__device__ __align__(16) float g_W [PTOT*DD];   // pair states
__device__ __align__(16) float g_h1[PTOT*DD];   // h1[b,u,w,d]
__device__ __align__(16) float g_h2[PTOT*DD];   // h2t[b,v,w,d] = adj[b,w,v]*h2[b,w,v,d]
__device__ __align__(16) float g_M [PTOT*DD];   // M, then reused as T (pre-norm)
__device__ int   g_aux[PTOT];
__device__ int   g_A  [PTOT];
__device__ float g_adj[PTOT];
__device__ float g_sum[BB*DD];
__device__ float g_sq [BB*DD];
__device__ float g_scale[BB*DD];
__device__ float g_shift[BB*DD];
__device__ float g_pool[BB*DD];

// ---------------------------------------------------------------------------
__global__ void k_init_clear() {
    int i = blockIdx.x * 256 + threadIdx.x;
    if (i < PTOT)   g_aux[i] = -1;
    if (i < BB*DD)  g_pool[i] = 0.0f;
}

// Reproduce JAX sequential scatter semantics:
// phase 1: A[g,u,v]=ea (edge order), phase 2: A[g,v,u]=ea (edge order).
// Later writes win -> atomicMax on packed key (phase*BEP+e)<<3 | label.
__global__ void k_scatter(const int* __restrict__ ei, const int* __restrict__ ea) {
    int e = blockIdx.x * 256 + threadIdx.x;
    if (e >= BEP) return;
    int a = ei[e];
    int bnode = ei[BEP + e];
    int g = a / NN, u = a % NN, v = bnode % NN;
    int lab = ea[e] & 7;
    atomicMax(&g_aux[g*NPAIR + u*NN + v], (e << 3) | lab);
    atomicMax(&g_aux[g*NPAIR + v*NN + u], ((e + BEP) << 3) | lab);
}

__global__ void k_decode() {
    int i = blockIdx.x * 256 + threadIdx.x;
    if (i >= PTOT) return;
    int av = g_aux[i];
    int a  = (av < 0) ? EV : (av & 7);
    g_A[i]   = a;
    g_adj[i] = (a != EV) ? 1.0f : 0.0f;
}

// W[b,u,v,:] = node_emb[x[bu]] + node_emb[x[bv]] + edge_emb[A[b,u,v]]
__global__ void k_initW(const int* __restrict__ x,
                        const float* __restrict__ nemb,
                        const float* __restrict__ eemb) {
    long q = (long)blockIdx.x * 256 + threadIdx.x;    // one float4 each
    int p  = (int)(q >> 4);
    int d0 = ((int)q & 15) << 2;
    int b = p / NPAIR, r = p % NPAIR, u = r / NN, v = r % NN;
    int xu = x[b*NN + u], xv = x[b*NN + v], a = g_A[p];
    float4 hu = *(const float4*)(nemb + xu*DD + d0);
    float4 hv = *(const float4*)(nemb + xv*DD + d0);
    float4 he = *(const float4*)(eemb + a*DD + d0);
    float4 o;
    o.x = hu.x + hv.x + he.x;
    o.y = hu.y + hv.y + he.y;
    o.z = hu.z + hv.z + he.z;
    o.w = hu.w + hv.w + he.w;
    *(float4*)(g_W + (long)p*DD + d0) = o;
}

__global__ void k_clear_stats() {
    int i = blockIdx.x * 256 + threadIdx.x;
    if (i < BB*DD) { g_sum[i] = 0.0f; g_sq[i] = 0.0f; }
}

// ---------------------------------------------------------------------------
// K1: h1 = relu(W@W1+b1); h2t[b,v,w,:] = adj[b,w,v]*relu(W[b,w,v,:]@W2+b2)
// 64 rows x 128 cols per block, 256 threads, each 8 rows x 4 cols.
__global__ void __launch_bounds__(256) k1_gemm(const float* __restrict__ W1,
                                               const float* __restrict__ b1,
                                               const float* __restrict__ W2,
                                               const float* __restrict__ b2) {
    __shared__ float sIn[64][64];
    __shared__ float sWc[64][128];
    __shared__ float sB[128];
    int t = threadIdx.x;
    for (int i = t; i < 4096; i += 256) {
        int k = i >> 6, c = i & 63;
        sWc[k][c]      = W1[i];
        sWc[k][64 + c] = W2[i];
    }
    if (t < 64) sB[t] = b1[t];
    else if (t < 128) sB[t] = b2[t - 64];
    long base = (long)blockIdx.x * 4096;
    const float4* src = (const float4*)(g_W + base);
    float4* sdst = (float4*)&sIn[0][0];
    for (int i = t; i < 1024; i += 256) sdst[i] = src[i];
    __syncthreads();

    int cg = (t & 31) * 4;          // 0..124
    int rg = (t >> 5) * 8;          // 0..56
    float acc[8][4];
#pragma unroll
    for (int i = 0; i < 8; i++)
#pragma unroll
        for (int j = 0; j < 4; j++) acc[i][j] = 0.0f;

#pragma unroll 16
    for (int k = 0; k < 64; k++) {
        float4 w = *(float4*)&sWc[k][cg];
#pragma unroll
        for (int i = 0; i < 8; i++) {
            float a = sIn[rg + i][k];
            acc[i][0] = fmaf(a, w.x, acc[i][0]);
            acc[i][1] = fmaf(a, w.y, acc[i][1]);
            acc[i][2] = fmaf(a, w.z, acc[i][2]);
            acc[i][3] = fmaf(a, w.w, acc[i][3]);
        }
    }
    float4 bb = *(float4*)&sB[cg];
    int prow0 = blockIdx.x * 64;
    if (cg < 64) {
#pragma unroll
        for (int i = 0; i < 8; i++) {
            int p = prow0 + rg + i;
            float4 o;
            o.x = fmaxf(acc[i][0] + bb.x, 0.0f);
            o.y = fmaxf(acc[i][1] + bb.y, 0.0f);
            o.z = fmaxf(acc[i][2] + bb.z, 0.0f);
            o.w = fmaxf(acc[i][3] + bb.w, 0.0f);
            *(float4*)(g_h1 + (long)p*64 + cg) = o;
        }
    } else {
        int c2 = cg - 64;
#pragma unroll
        for (int i = 0; i < 8; i++) {
            int p = prow0 + rg + i;
            int b = p / NPAIR, r = p % NPAIR, w2 = r / NN, v = r % NN;
            float ad = g_adj[p];
            float4 o;
            o.x = fmaxf(acc[i][0] + bb.x, 0.0f) * ad;
            o.y = fmaxf(acc[i][1] + bb.y, 0.0f) * ad;
            o.z = fmaxf(acc[i][2] + bb.z, 0.0f) * ad;
            o.w = fmaxf(acc[i][3] + bb.w, 0.0f) * ad;
            int q = b*NPAIR + v*NN + w2;
            *(float4*)(g_h2 + (long)q*64 + c2) = o;
        }
    }
}

// ---------------------------------------------------------------------------
// K2: M[b,u,v,d] = sum_w h1[b,u,w,d] * h2t[b,v,w,d]
// block: (b, 16 u, 16 v, 64 d); thread = (d, u-quad)
__global__ void __launch_bounds__(256) k2_M() {
    __shared__ float sA[16][64];
    __shared__ float sG[16][64];
    int t = threadIdx.x;
    int bid = blockIdx.x;
    int b = bid / 36, r = bid % 36, ui = r / 6, vi = r % 6;
    int u0 = ui * 16, v0 = vi * 16;
    const float* h1base = g_h1 + ((long)b*NPAIR + (long)u0*NN) * DD;
    const float* h2base = g_h2 + ((long)b*NPAIR + (long)v0*NN) * DD;
    int d = t & 63, grp = t >> 6;
    int li = t >> 4, lj = t & 15;
    float acc[4][16];
#pragma unroll
    for (int i = 0; i < 4; i++)
#pragma unroll
        for (int j = 0; j < 16; j++) acc[i][j] = 0.0f;

    for (int w = 0; w < 96; w++) {
        float4 va = *(const float4*)(h1base + (long)li*6144 + w*64 + lj*4);
        float4 vg = *(const float4*)(h2base + (long)li*6144 + w*64 + lj*4);
        ((float4*)&sA[li][0])[lj] = va;
        ((float4*)&sG[li][0])[lj] = vg;
        __syncthreads();
        float gv[16];
#pragma unroll
        for (int j = 0; j < 16; j++) gv[j] = sG[j][d];
#pragma unroll
        for (int i = 0; i < 4; i++) {
            float a = sA[grp*4 + i][d];
#pragma unroll
            for (int j = 0; j < 16; j++) acc[i][j] = fmaf(a, gv[j], acc[i][j]);
        }
        __syncthreads();
    }
    float* Mb = g_M + (long)b*NPAIR*DD;
#pragma unroll
    for (int i = 0; i < 4; i++) {
        int u = u0 + grp*4 + i;
#pragma unroll
        for (int j = 0; j < 16; j++)
            Mb[((long)u*NN + (v0 + j))*DD + d] = acc[i][j];
    }
}

// ---------------------------------------------------------------------------
// K3: T = W + M@Wm + bm (written back into g_M), accumulate per-(b,d) stats.
__global__ void __launch_bounds__(256) k3_update(const float* __restrict__ Wm,
                                                 const float* __restrict__ bm) {
    __shared__ float sIn[64][68];
    __shared__ float sWm[64][64];
    __shared__ float sBm[64];
    __shared__ float sSum[64], sSq[64];
    int t = threadIdx.x;
    for (int i = t; i < 4096; i += 256) sWm[i >> 6][i & 63] = Wm[i];
    if (t < 64) { sBm[t] = bm[t]; sSum[t] = 0.0f; sSq[t] = 0.0f; }
    long base = (long)blockIdx.x * 4096;
    const float4* src = (const float4*)(g_M + base);
    for (int i = t; i < 1024; i += 256) {
        float4 v = src[i];
        int r = i >> 4, j = (i & 15) << 2;
        sIn[r][j] = v.x; sIn[r][j+1] = v.y; sIn[r][j+2] = v.z; sIn[r][j+3] = v.w;
    }
    __syncthreads();

    int cg = (t & 15) * 4, rg = (t >> 4) * 4;
    float acc[4][4];
#pragma unroll
    for (int i = 0; i < 4; i++)
#pragma unroll
        for (int j = 0; j < 4; j++) acc[i][j] = 0.0f;
#pragma unroll 16
    for (int k = 0; k < 64; k++) {
        float4 w = *(float4*)&sWm[k][cg];
#pragma unroll
        for (int i = 0; i < 4; i++) {
            float a = sIn[rg + i][k];
            acc[i][0] = fmaf(a, w.x, acc[i][0]);
            acc[i][1] = fmaf(a, w.y, acc[i][1]);
            acc[i][2] = fmaf(a, w.z, acc[i][2]);
            acc[i][3] = fmaf(a, w.w, acc[i][3]);
        }
    }
    float4 bb = *(float4*)&sBm[cg];
    float cs0=0,cs1=0,cs2=0,cs3=0,cq0=0,cq1=0,cq2=0,cq3=0;
#pragma unroll
    for (int i = 0; i < 4; i++) {
        int p = blockIdx.x * 64 + rg + i;
        float4 wv = *(const float4*)(g_W + (long)p*64 + cg);
        float4 o;
        o.x = acc[i][0] + bb.x + wv.x;
        o.y = acc[i][1] + bb.y + wv.y;
        o.z = acc[i][2] + bb.z + wv.z;
        o.w = acc[i][3] + bb.w + wv.w;
        *(float4*)(g_M + (long)p*64 + cg) = o;
        cs0 += o.x; cq0 += o.x*o.x;
        cs1 += o.y; cq1 += o.y*o.y;
        cs2 += o.z; cq2 += o.z*o.z;
        cs3 += o.w; cq3 += o.w*o.w;
    }
    atomicAdd(&sSum[cg+0], cs0); atomicAdd(&sSq[cg+0], cq0);
    atomicAdd(&sSum[cg+1], cs1); atomicAdd(&sSq[cg+1], cq1);
    atomicAdd(&sSum[cg+2], cs2); atomicAdd(&sSq[cg+2], cq2);
    atomicAdd(&sSum[cg+3], cs3); atomicAdd(&sSq[cg+3], cq3);
    __syncthreads();
    if (t < 64) {
        int b = blockIdx.x / 144;
        atomicAdd(&g_sum[b*64 + t], sSum[t]);
        atomicAdd(&g_sq [b*64 + t], sSq[t]);
    }
}

__global__ void k_stats(const float* __restrict__ gamma,
                        const float* __restrict__ beta) {
    int i = blockIdx.x * 256 + threadIdx.x;
    if (i >= BB*DD) return;
    int d = i & 63;
    float mu  = g_sum[i] * (1.0f / NPAIR);
    float var = g_sq[i]  * (1.0f / NPAIR) - mu*mu;
    float sc  = gamma[d] * rsqrtf(var + 1e-5f);
    g_scale[i] = sc;
    g_shift[i] = beta[d] - mu * sc;
}

// K4: W = relu(T*scale + shift); on last layer accumulate pooled sums.
__global__ void __launch_bounds__(256) k4_norm(int last) {
    __shared__ float sp[64];
    int t = threadIdx.x;
    long q = (long)blockIdx.x * 256 + t;
    long idx = q * 4;
    int d0 = (int)(idx & 63);
    int p  = (int)(idx >> 6);
    int b  = p / NPAIR;
    float4 v  = *(const float4*)(g_M + idx);
    float4 sc = *(const float4*)(g_scale + b*64 + d0);
    float4 sh = *(const float4*)(g_shift + b*64 + d0);
    float4 o;
    o.x = fmaxf(fmaf(v.x, sc.x, sh.x), 0.0f);
    o.y = fmaxf(fmaf(v.y, sc.y, sh.y), 0.0f);
    o.z = fmaxf(fmaf(v.z, sc.z, sh.z), 0.0f);
    o.w = fmaxf(fmaf(v.w, sc.w, sh.w), 0.0f);
    *(float4*)(g_W + idx) = o;
    if (last) {
        if (t < 64) sp[t] = 0.0f;
        __syncthreads();
        atomicAdd(&sp[d0+0], o.x);
        atomicAdd(&sp[d0+1], o.y);
        atomicAdd(&sp[d0+2], o.z);
        atomicAdd(&sp[d0+3], o.w);
        __syncthreads();
        if (t < 64) atomicAdd(&g_pool[b*64 + t], sp[t]);
    }
}

__global__ void k5_out(const float* __restrict__ pw,
                       const float* __restrict__ pb,
                       float* __restrict__ out) {
    int t = threadIdx.x;          // 1024 threads, warp per graph
    int b = t >> 5, lane = t & 31;
    float v = g_pool[b*64 + lane]      * pw[lane]
            + g_pool[b*64 + lane + 32] * pw[lane + 32];
#pragma unroll
    for (int o = 16; o > 0; o >>= 1) v += __shfl_down_sync(0xffffffffu, v, o);
    if (lane == 0) out[b] = v + pb[0];
}

// ---------------------------------------------------------------------------
extern "C" void kernel_launch(void* const* d_in, const int* in_sizes, int n_in,
                              void* d_out, int out_size) {
    (void)in_sizes; (void)n_in; (void)out_size;
    const int*   x    = (const int*)d_in[0];
    const int*   ei   = (const int*)d_in[1];
    const int*   ea   = (const int*)d_in[2];
    const float* nemb = (const float*)d_in[3];
    const float* eemb = (const float*)d_in[4];
    const float* W1   = (const float*)d_in[5];
    const float* b1   = (const float*)d_in[6];
    const float* W2   = (const float*)d_in[7];
    const float* b2   = (const float*)d_in[8];
    const float* Wm   = (const float*)d_in[9];
    const float* bm   = (const float*)d_in[10];
    const float* gam  = (const float*)d_in[11];
    const float* bet  = (const float*)d_in[12];
    const float* pw   = (const float*)d_in[13];
    const float* pb   = (const float*)d_in[14];
    float* out = (float*)d_out;

    k_init_clear<<<1152, 256>>>();
    k_scatter<<<96, 256>>>(ei, ea);
    k_decode<<<1152, 256>>>();
    k_initW<<<18432, 256>>>(x, nemb, eemb);

    for (int l = 0; l < LL; l++) {
        k_clear_stats<<<8, 256>>>();
        k1_gemm<<<4608, 256>>>(W1 + l*4096, b1 + l*64, W2 + l*4096, b2 + l*64);
        k2_M<<<1152, 256>>>();
        k3_update<<<4608, 256>>>(Wm + l*4096, bm + l*64);
        k_stats<<<8, 256>>>(gam + l*64, bet + l*64);
        k4_norm<<<18432, 256>>>(l == LL-1 ? 1 : 0);
    }
    k5_out<<<1, 1024>>>(pw, pb, out);
}

// round 2
// speedup vs baseline: 1.9603x; 1.9603x over previous
#include <cuda_runtime.h>

#define BB    32
#define NN    96
#define DD    64
#define LL    5
#define NPAIR 9216            // N*N
#define PTOT  294912          // B*N*N
#define BEP   24576           // B*EP
#define EV    5
#define MAXPAIRS 49152        // <= 2*EP per graph * B

// ---- scratch (device globals; no allocation allowed) ----
__device__ __align__(16) float g_T0 [PTOT*DD];  // pair-state ping
__device__ __align__(16) float g_T1 [PTOT*DD];  // pair-state pong (also holds init W)
__device__ __align__(16) float g_h1 [PTOT*DD];  // h1[b,u,w,d] dense
__device__ __align__(16) float g_h2 [PTOT*DD];  // h2[b,w,v,d] (edge slots only valid)
__device__ __align__(16) float g_M  [PTOT*DD];  // aggregation output
__device__ int   g_aux[PTOT];
__device__ int   g_A  [PTOT];
__device__ int   g_deg[BB*NN];
__device__ int   g_nbr[BB*NN*NN];
__device__ int   g_pairs[MAXPAIRS];
__device__ int   g_npairs;
__device__ float g_sum[BB*DD];
__device__ float g_sq [BB*DD];
__device__ float g_scale[BB*DD];
__device__ float g_shift[BB*DD];
__device__ float g_pool[BB*DD];

// ---------------------------------------------------------------------------
__global__ void k_init_clear() {
    int i = blockIdx.x * 256 + threadIdx.x;
    if (i < PTOT)   g_aux[i] = -1;
    if (i < BB*DD)  g_pool[i] = 0.0f;
    if (i < BB*NN)  g_deg[i] = 0;
    if (i == 0)     g_npairs = 0;
}

// Reproduce JAX sequential scatter semantics (last write wins).
__global__ void k_scatter(const int* __restrict__ ei, const int* __restrict__ ea) {
    int e = blockIdx.x * 256 + threadIdx.x;
    if (e >= BEP) return;
    int a = ei[e];
    int bnode = ei[BEP + e];
    int g = a / NN, u = a % NN, v = bnode % NN;
    int lab = ea[e] & 7;
    atomicMax(&g_aux[g*NPAIR + u*NN + v], (e << 3) | lab);
    atomicMax(&g_aux[g*NPAIR + v*NN + u], ((e + BEP) << 3) | lab);
}

// Decode labels + build CSR neighbor lists (per column v) + edge-pair list.
__global__ void k_decode() {
    int i = blockIdx.x * 256 + threadIdx.x;
    if (i >= PTOT) return;
    int av = g_aux[i];
    int a  = (av < 0) ? EV : (av & 7);
    g_A[i] = a;
    if (a != EV) {
        int b = i / NPAIR, r = i % NPAIR;
        int w = r / NN, v = r % NN;           // entry A[b,w,v]
        int slot = atomicAdd(&g_deg[b*NN + v], 1);
        g_nbr[(b*NN + v)*NN + slot] = w;
        int ps = atomicAdd(&g_npairs, 1);
        g_pairs[ps] = i;
    }
}

// W0[b,u,v,:] = node_emb[x[bu]] + node_emb[x[bv]] + edge_emb[A[b,u,v]]  -> g_T1
__global__ void k_initW(const int* __restrict__ x,
                        const float* __restrict__ nemb,
                        const float* __restrict__ eemb) {
    long q = (long)blockIdx.x * 256 + threadIdx.x;
    int p  = (int)(q >> 4);
    int d0 = ((int)q & 15) << 2;
    int b = p / NPAIR, r = p % NPAIR, u = r / NN, v = r % NN;
    int xu = x[b*NN + u], xv = x[b*NN + v], a = g_A[p];
    float4 hu = *(const float4*)(nemb + xu*DD + d0);
    float4 hv = *(const float4*)(nemb + xv*DD + d0);
    float4 he = *(const float4*)(eemb + a*DD + d0);
    float4 o;
    o.x = hu.x + hv.x + he.x;
    o.y = hu.y + hv.y + he.y;
    o.z = hu.z + hv.z + he.z;
    o.w = hu.w + hv.w + he.w;
    *(float4*)(g_T1 + (long)p*DD + d0) = o;
}

__global__ void k_clear_stats() {
    int i = blockIdx.x * 256 + threadIdx.x;
    if (i < BB*DD) { g_sum[i] = 0.0f; g_sq[i] = 0.0f; }
}

// ---------------------------------------------------------------------------
// K1h1: h1 = relu( relu_norm(Tprev) @ W1 + b1 )  for ALL pairs.
// 64 rows x 64 cols per block, 256 threads (4x4 per thread).
__global__ void __launch_bounds__(256) k1h1(const float* __restrict__ Tprev,
                                            const float* __restrict__ Wt,
                                            const float* __restrict__ bt,
                                            int useNorm) {
    __shared__ float sIn[64][68];
    __shared__ float sW[64][64];
    __shared__ float sB[64];
    int t = threadIdx.x;
    int b = blockIdx.x / 144;
    for (int i = t; i < 4096; i += 256) sW[i >> 6][i & 63] = Wt[i];
    if (t < 64) sB[t] = bt[t];
    long base = (long)blockIdx.x * 4096;
    for (int i = t; i < 1024; i += 256) {
        float4 v = *(const float4*)(Tprev + base + (long)i*4);
        int r = i >> 4, j = (i & 15) << 2;
        if (useNorm) {
            float4 sc = *(const float4*)(g_scale + b*64 + j);
            float4 sh = *(const float4*)(g_shift + b*64 + j);
            v.x = fmaxf(fmaf(v.x, sc.x, sh.x), 0.0f);
            v.y = fmaxf(fmaf(v.y, sc.y, sh.y), 0.0f);
            v.z = fmaxf(fmaf(v.z, sc.z, sh.z), 0.0f);
            v.w = fmaxf(fmaf(v.w, sc.w, sh.w), 0.0f);
        }
        sIn[r][j] = v.x; sIn[r][j+1] = v.y; sIn[r][j+2] = v.z; sIn[r][j+3] = v.w;
    }
    __syncthreads();

    int cg = (t & 15) * 4, rg = (t >> 4) * 4;
    float acc[4][4];
#pragma unroll
    for (int i = 0; i < 4; i++)
#pragma unroll
        for (int j = 0; j < 4; j++) acc[i][j] = 0.0f;
#pragma unroll 16
    for (int k = 0; k < 64; k++) {
        float4 w = *(float4*)&sW[k][cg];
#pragma unroll
        for (int i = 0; i < 4; i++) {
            float a = sIn[rg + i][k];
            acc[i][0] = fmaf(a, w.x, acc[i][0]);
            acc[i][1] = fmaf(a, w.y, acc[i][1]);
            acc[i][2] = fmaf(a, w.z, acc[i][2]);
            acc[i][3] = fmaf(a, w.w, acc[i][3]);
        }
    }
    float4 bb = *(float4*)&sB[cg];
#pragma unroll
    for (int i = 0; i < 4; i++) {
        int p = blockIdx.x * 64 + rg + i;
        float4 o;
        o.x = fmaxf(acc[i][0] + bb.x, 0.0f);
        o.y = fmaxf(acc[i][1] + bb.y, 0.0f);
        o.z = fmaxf(acc[i][2] + bb.z, 0.0f);
        o.w = fmaxf(acc[i][3] + bb.w, 0.0f);
        *(float4*)(g_h1 + (long)p*64 + cg) = o;
    }
}

// K1h2: gathered GEMM over edge-pair rows only (<=16.7% of pairs).
__global__ void __launch_bounds__(256) k1h2(const float* __restrict__ Tprev,
                                            const float* __restrict__ Wt,
                                            const float* __restrict__ bt,
                                            int useNorm) {
    __shared__ float sIn[64][68];
    __shared__ float sW[64][64];
    __shared__ float sB[64];
    __shared__ int sP[64];
    int t = threadIdx.x;
    int np = g_npairs;
    for (int i = t; i < 4096; i += 256) sW[i >> 6][i & 63] = Wt[i];
    if (t < 64) {
        sB[t] = bt[t];
        int r = blockIdx.x * 64 + t;
        sP[t] = (r < np) ? g_pairs[r] : -1;
    }
    __syncthreads();
    for (int i = t; i < 1024; i += 256) {
        int r = i >> 4, j = (i & 15) << 2;
        int p = sP[r];
        float4 v = make_float4(0.f, 0.f, 0.f, 0.f);
        if (p >= 0) {
            v = *(const float4*)(Tprev + (long)p*64 + j);
            if (useNorm) {
                int bb = p / NPAIR;
                float4 sc = *(const float4*)(g_scale + bb*64 + j);
                float4 sh = *(const float4*)(g_shift + bb*64 + j);
                v.x = fmaxf(fmaf(v.x, sc.x, sh.x), 0.0f);
                v.y = fmaxf(fmaf(v.y, sc.y, sh.y), 0.0f);
                v.z = fmaxf(fmaf(v.z, sc.z, sh.z), 0.0f);
                v.w = fmaxf(fmaf(v.w, sc.w, sh.w), 0.0f);
            }
        }
        sIn[r][j] = v.x; sIn[r][j+1] = v.y; sIn[r][j+2] = v.z; sIn[r][j+3] = v.w;
    }
    __syncthreads();

    int cg = (t & 15) * 4, rg = (t >> 4) * 4;
    float acc[4][4];
#pragma unroll
    for (int i = 0; i < 4; i++)
#pragma unroll
        for (int j = 0; j < 4; j++) acc[i][j] = 0.0f;
#pragma unroll 16
    for (int k = 0; k < 64; k++) {
        float4 w = *(float4*)&sW[k][cg];
#pragma unroll
        for (int i = 0; i < 4; i++) {
            float a = sIn[rg + i][k];
            acc[i][0] = fmaf(a, w.x, acc[i][0]);
            acc[i][1] = fmaf(a, w.y, acc[i][1]);
            acc[i][2] = fmaf(a, w.z, acc[i][2]);
            acc[i][3] = fmaf(a, w.w, acc[i][3]);
        }
    }
    float4 bb = *(float4*)&sB[cg];
#pragma unroll
    for (int i = 0; i < 4; i++) {
        int p = sP[rg + i];
        if (p >= 0) {
            float4 o;
            o.x = fmaxf(acc[i][0] + bb.x, 0.0f);
            o.y = fmaxf(acc[i][1] + bb.y, 0.0f);
            o.z = fmaxf(acc[i][2] + bb.z, 0.0f);
            o.w = fmaxf(acc[i][3] + bb.w, 0.0f);
            *(float4*)(g_h2 + (long)p*64 + cg) = o;
        }
    }
}

// ---------------------------------------------------------------------------
// K2 sparse: M[b,u,v,d] = sum_{w in N(v)} h1[b,u,w,d] * h2[b,w,v,d]
// one block per (b,v); h2 neighbor rows staged in smem; h1 gathered (L2-hot).
__global__ void __launch_bounds__(256) k2_sparse() {
    __shared__ int snbr[96];
    __shared__ float sh2[96*64];
    int t = threadIdx.x;
    int b = blockIdx.x / NN, v = blockIdx.x % NN;
    int deg = g_deg[b*NN + v];
    if (t < 96) snbr[t] = (t < deg) ? g_nbr[(b*NN + v)*NN + t] : 0;
    __syncthreads();
    for (int q = t; q < deg*16; q += 256) {
        int s = q >> 4, j = (q & 15) << 2;
        int w = snbr[s];
        *(float4*)&sh2[s*64 + j] =
            *(const float4*)(g_h2 + ((long)(b*NPAIR + w*NN + v) << 6) + j);
    }
    __syncthreads();

    int d0 = (t & 15) * 4, ug = t >> 4;      // ug 0..15, each owns 6 u's
    float4 acc[6];
#pragma unroll
    for (int i = 0; i < 6; i++) acc[i] = make_float4(0.f,0.f,0.f,0.f);

    const float* h1b = g_h1 + ((long)b*NPAIR << 6) + (long)ug*6*6144 + d0;
    for (int s = 0; s < deg; s++) {
        int w = snbr[s];
        float4 h2v = *(float4*)&sh2[s*64 + d0];
        const float* p0 = h1b + (long)w*64;
#pragma unroll
        for (int i = 0; i < 6; i++) {
            float4 a = *(const float4*)(p0 + (long)i*6144);
            acc[i].x = fmaf(a.x, h2v.x, acc[i].x);
            acc[i].y = fmaf(a.y, h2v.y, acc[i].y);
            acc[i].z = fmaf(a.z, h2v.z, acc[i].z);
            acc[i].w = fmaf(a.w, h2v.w, acc[i].w);
        }
    }
    float* Mb = g_M + ((long)(b*NPAIR + v) << 6) + (long)ug*6*6144 + d0;
#pragma unroll
    for (int i = 0; i < 6; i++)
        *(float4*)(Mb + (long)i*6144) = acc[i];
}

// ---------------------------------------------------------------------------
// K3: Tcur = relu_norm(Tprev) + M@Wm + bm ; accumulate per-(b,d) stats.
__global__ void __launch_bounds__(256) k3_update(const float* __restrict__ Tprev,
                                                 const float* __restrict__ Wm,
                                                 const float* __restrict__ bm,
                                                 int useNorm,
                                                 float* __restrict__ Tcur) {
    __shared__ float sIn[64][68];
    __shared__ float sWm[64][64];
    __shared__ float sBm[64];
    __shared__ float sSum[64], sSq[64];
    int t = threadIdx.x;
    int b = blockIdx.x / 144;
    for (int i = t; i < 4096; i += 256) sWm[i >> 6][i & 63] = Wm[i];
    if (t < 64) { sBm[t] = bm[t]; sSum[t] = 0.0f; sSq[t] = 0.0f; }
    long base = (long)blockIdx.x * 4096;
    for (int i = t; i < 1024; i += 256) {
        float4 v = *(const float4*)(g_M + base + (long)i*4);
        int r = i >> 4, j = (i & 15) << 2;
        sIn[r][j] = v.x; sIn[r][j+1] = v.y; sIn[r][j+2] = v.z; sIn[r][j+3] = v.w;
    }
    __syncthreads();

    int cg = (t & 15) * 4, rg = (t >> 4) * 4;
    float acc[4][4];
#pragma unroll
    for (int i = 0; i < 4; i++)
#pragma unroll
        for (int j = 0; j < 4; j++) acc[i][j] = 0.0f;
#pragma unroll 16
    for (int k = 0; k < 64; k++) {
        float4 w = *(float4*)&sWm[k][cg];
#pragma unroll
        for (int i = 0; i < 4; i++) {
            float a = sIn[rg + i][k];
            acc[i][0] = fmaf(a, w.x, acc[i][0]);
            acc[i][1] = fmaf(a, w.y, acc[i][1]);
            acc[i][2] = fmaf(a, w.z, acc[i][2]);
            acc[i][3] = fmaf(a, w.w, acc[i][3]);
        }
    }
    float4 bb = *(float4*)&sBm[cg];
    float4 sc = make_float4(1.f,1.f,1.f,1.f), sh = make_float4(0.f,0.f,0.f,0.f);
    if (useNorm) {
        sc = *(const float4*)(g_scale + b*64 + cg);
        sh = *(const float4*)(g_shift + b*64 + cg);
    }
    float cs0=0,cs1=0,cs2=0,cs3=0,cq0=0,cq1=0,cq2=0,cq3=0;
#pragma unroll
    for (int i = 0; i < 4; i++) {
        int p = blockIdx.x * 64 + rg + i;
        float4 wv = *(const float4*)(Tprev + (long)p*64 + cg);
        if (useNorm) {
            wv.x = fmaxf(fmaf(wv.x, sc.x, sh.x), 0.0f);
            wv.y = fmaxf(fmaf(wv.y, sc.y, sh.y), 0.0f);
            wv.z = fmaxf(fmaf(wv.z, sc.z, sh.z), 0.0f);
            wv.w = fmaxf(fmaf(wv.w, sc.w, sh.w), 0.0f);
        }
        float4 o;
        o.x = acc[i][0] + bb.x + wv.x;
        o.y = acc[i][1] + bb.y + wv.y;
        o.z = acc[i][2] + bb.z + wv.z;
        o.w = acc[i][3] + bb.w + wv.w;
        *(float4*)(Tcur + (long)p*64 + cg) = o;
        cs0 += o.x; cq0 += o.x*o.x;
        cs1 += o.y; cq1 += o.y*o.y;
        cs2 += o.z; cq2 += o.z*o.z;
        cs3 += o.w; cq3 += o.w*o.w;
    }
    atomicAdd(&sSum[cg+0], cs0); atomicAdd(&sSq[cg+0], cq0);
    atomicAdd(&sSum[cg+1], cs1); atomicAdd(&sSq[cg+1], cq1);
    atomicAdd(&sSum[cg+2], cs2); atomicAdd(&sSq[cg+2], cq2);
    atomicAdd(&sSum[cg+3], cs3); atomicAdd(&sSq[cg+3], cq3);
    __syncthreads();
    if (t < 64) {
        atomicAdd(&g_sum[b*64 + t], sSum[t]);
        atomicAdd(&g_sq [b*64 + t], sSq[t]);
    }
}

__global__ void k_stats(const float* __restrict__ gamma,
                        const float* __restrict__ beta) {
    int i = blockIdx.x * 256 + threadIdx.x;
    if (i >= BB*DD) return;
    int d = i & 63;
    float mu  = g_sum[i] * (1.0f / NPAIR);
    float var = g_sq[i]  * (1.0f / NPAIR) - mu*mu;
    float s   = gamma[d] * rsqrtf(var + 1e-5f);
    g_scale[i] = s;
    g_shift[i] = beta[d] - mu * s;
}

// Final pooling: sum over pairs of relu(norm(Tlast)) per (b,d).
__global__ void __launch_bounds__(256) k_pool(const float* __restrict__ T) {
    __shared__ float sp[64];
    int t = threadIdx.x;
    long q = (long)blockIdx.x * 256 + t;
    long idx = q * 4;
    int d0 = (int)(idx & 63);
    int p  = (int)(idx >> 6);
    int b  = p / NPAIR;
    float4 v  = *(const float4*)(T + idx);
    float4 sc = *(const float4*)(g_scale + b*64 + d0);
    float4 sh = *(const float4*)(g_shift + b*64 + d0);
    float4 o;
    o.x = fmaxf(fmaf(v.x, sc.x, sh.x), 0.0f);
    o.y = fmaxf(fmaf(v.y, sc.y, sh.y), 0.0f);
    o.z = fmaxf(fmaf(v.z, sc.z, sh.z), 0.0f);
    o.w = fmaxf(fmaf(v.w, sc.w, sh.w), 0.0f);
    if (t < 64) sp[t] = 0.0f;
    __syncthreads();
    atomicAdd(&sp[d0+0], o.x);
    atomicAdd(&sp[d0+1], o.y);
    atomicAdd(&sp[d0+2], o.z);
    atomicAdd(&sp[d0+3], o.w);
    __syncthreads();
    if (t < 64) atomicAdd(&g_pool[b*64 + t], sp[t]);
}

__global__ void k5_out(const float* __restrict__ pw,
                       const float* __restrict__ pb,
                       float* __restrict__ out) {
    int t = threadIdx.x;
    int b = t >> 5, lane = t & 31;
    float v = g_pool[b*64 + lane]      * pw[lane]
            + g_pool[b*64 + lane + 32] * pw[lane + 32];
#pragma unroll
    for (int o = 16; o > 0; o >>= 1) v += __shfl_down_sync(0xffffffffu, v, o);
    if (lane == 0) out[b] = v + pb[0];
}

// ---------------------------------------------------------------------------
extern "C" void kernel_launch(void* const* d_in, const int* in_sizes, int n_in,
                              void* d_out, int out_size) {
    (void)in_sizes; (void)n_in; (void)out_size;
    const int*   x    = (const int*)d_in[0];
    const int*   ei   = (const int*)d_in[1];
    const int*   ea   = (const int*)d_in[2];
    const float* nemb = (const float*)d_in[3];
    const float* eemb = (const float*)d_in[4];
    const float* W1   = (const float*)d_in[5];
    const float* b1   = (const float*)d_in[6];
    const float* W2   = (const float*)d_in[7];
    const float* b2   = (const float*)d_in[8];
    const float* Wm   = (const float*)d_in[9];
    const float* bm   = (const float*)d_in[10];
    const float* gam  = (const float*)d_in[11];
    const float* bet  = (const float*)d_in[12];
    const float* pw   = (const float*)d_in[13];
    const float* pb   = (const float*)d_in[14];
    float* out = (float*)d_out;

    float* gT0; cudaGetSymbolAddress((void**)&gT0, g_T0);
    float* gT1; cudaGetSymbolAddress((void**)&gT1, g_T1);

    k_init_clear<<<1152, 256>>>();
    k_scatter<<<96, 256>>>(ei, ea);
    k_decode<<<1152, 256>>>();
    k_initW<<<18432, 256>>>(x, nemb, eemb);   // writes g_T1

    for (int l = 0; l < LL; l++) {
        float* Tprev = (l % 2 == 0) ? gT1 : gT0;
        float* Tcur  = (l % 2 == 0) ? gT0 : gT1;
        int useNorm  = (l > 0) ? 1 : 0;
        k_clear_stats<<<8, 256>>>();
        k1h1<<<4608, 256>>>(Tprev, W1 + l*4096, b1 + l*64, useNorm);
        k1h2<<<768, 256>>>(Tprev, W2 + l*4096, b2 + l*64, useNorm);
        k2_sparse<<<3072, 256>>>();
        k3_update<<<4608, 256>>>(Tprev, Wm + l*4096, bm + l*64, useNorm, Tcur);
        k_stats<<<8, 256>>>(gam + l*64, bet + l*64);
    }
    // last layer (l=4) wrote Tcur = g_T0; its stats are in g_scale/g_shift
    k_pool<<<18432, 256>>>(gT0);
    k5_out<<<1, 1024>>>(pw, pb, out);
}

// round 4
// speedup vs baseline: 2.3333x; 1.1903x over previous
#include <cuda_runtime.h>
#include <cuda_fp16.h>

#define BB    32
#define NN    96
#define DD    64
#define LL    5
#define NPAIR 9216            // N*N
#define PTOT  294912          // B*N*N
#define BEP   24576           // B*EP
#define EV    5
#define MAXPAIRS 49152

// ---- scratch (device globals; no allocation allowed) ----
__device__ __align__(16) float g_T0 [PTOT*DD];
__device__ __align__(16) float g_T1 [PTOT*DD];
__device__ __align__(16) __half g_h1[PTOT*DD];          // h1[b,u,w,d] fp16
__device__ __align__(16) float  g_h2[PTOT*DD];          // h2[b,w,v,d] fp32 (edge slots)
__device__ __align__(16) float g_M  [PTOT*DD];
__device__ int   g_aux[PTOT];
__device__ int   g_A  [PTOT];
__device__ int   g_deg[BB*NN];
__device__ int   g_nbr[BB*NN*NN];
__device__ int   g_pairs[MAXPAIRS];
__device__ int   g_npairs;
__device__ float g_sum[BB*DD];
__device__ float g_sq [BB*DD];
__device__ float g_scale[BB*DD];
__device__ float g_shift[BB*DD];
__device__ float g_pool[BB*DD];

// smem layout for the big GEMM kernels (floats):
//  sInT[64][260] | sW[64][68] | sB[64] | sSum[64] | sSq[64]
#define SM_INT   (64*260)
#define SM_W     (64*68)
#define SM_TOTF  (SM_INT + SM_W + 64 + 64 + 64)

// ---------------------------------------------------------------------------
__global__ void k_init_clear() {
    int i = blockIdx.x * 256 + threadIdx.x;
    if (i < PTOT)   g_aux[i] = -1;
    if (i < BB*DD)  { g_pool[i] = 0.0f; g_sum[i] = 0.0f; g_sq[i] = 0.0f; }
    if (i < BB*NN)  g_deg[i] = 0;
    if (i == 0)     g_npairs = 0;
}

__global__ void k_scatter(const int* __restrict__ ei, const int* __restrict__ ea) {
    int e = blockIdx.x * 256 + threadIdx.x;
    if (e >= BEP) return;
    int a = ei[e];
    int bnode = ei[BEP + e];
    int g = a / NN, u = a % NN, v = bnode % NN;
    int lab = ea[e] & 7;
    atomicMax(&g_aux[g*NPAIR + u*NN + v], (e << 3) | lab);
    atomicMax(&g_aux[g*NPAIR + v*NN + u], ((e + BEP) << 3) | lab);
}

__global__ void k_decode() {
    int i = blockIdx.x * 256 + threadIdx.x;
    if (i >= PTOT) return;
    int av = g_aux[i];
    int a  = (av < 0) ? EV : (av & 7);
    g_A[i] = a;
    if (a != EV) {
        int b = i / NPAIR, r = i % NPAIR;
        int w = r / NN, v = r % NN;
        int slot = atomicAdd(&g_deg[b*NN + v], 1);
        g_nbr[(b*NN + v)*NN + slot] = w;
        int ps = atomicAdd(&g_npairs, 1);
        g_pairs[ps] = i;
    }
}

__global__ void k_initW(const int* __restrict__ x,
                        const float* __restrict__ nemb,
                        const float* __restrict__ eemb) {
    long q = (long)blockIdx.x * 256 + threadIdx.x;
    int p  = (int)(q >> 4);
    int d0 = ((int)q & 15) << 2;
    int b = p / NPAIR, r = p % NPAIR, u = r / NN, v = r % NN;
    int xu = x[b*NN + u], xv = x[b*NN + v], a = g_A[p];
    float4 hu = *(const float4*)(nemb + xu*DD + d0);
    float4 hv = *(const float4*)(nemb + xv*DD + d0);
    float4 he = *(const float4*)(eemb + a*DD + d0);
    float4 o;
    o.x = hu.x + hv.x + he.x;
    o.y = hu.y + hv.y + he.y;
    o.z = hu.z + hv.z + he.z;
    o.w = hu.w + hv.w + he.w;
    *(float4*)(g_T1 + (long)p*DD + d0) = o;
}

// ---------------------------------------------------------------------------
// K1h1: h1 = relu( relu_norm(Tprev) @ W1 + b1 ), output fp16.
// 256 rows x 64 cols per block; thread 8x8; input transposed in smem.
__global__ void __launch_bounds__(256) k1h1(const float* __restrict__ Tprev,
                                            const float* __restrict__ Wt,
                                            const float* __restrict__ bt,
                                            int useNorm) {
    extern __shared__ float sm[];
    float* sInT = sm;
    float* sW   = sm + SM_INT;
    float* sB   = sW + SM_W;
    int t = threadIdx.x;
    int b = blockIdx.x / 36;
    long base = (long)blockIdx.x * 256 * 64;

    for (int i = t; i < 4096; i += 256) sW[(i >> 6)*68 + (i & 63)] = Wt[i];
    if (t < 64) sB[t] = bt[t];

    int d  = t & 63;
    int r0 = (t >> 6) * 4;
    float sc = 1.f, sh = 0.f;
    if (useNorm) { sc = g_scale[b*64 + d]; sh = g_shift[b*64 + d]; }
#pragma unroll
    for (int it = 0; it < 16; it++) {
        int r = it*16 + r0;
#pragma unroll
        for (int q = 0; q < 4; q++) {
            float v = Tprev[base + (long)(r + q)*64 + d];
            if (useNorm) v = fmaxf(fmaf(v, sc, sh), 0.f);
            sInT[d*260 + r + q] = v;
        }
    }
    __syncthreads();

    int cg = (t & 7) * 8;
    int rg = (t >> 3) * 8;
    float acc[8][8];
#pragma unroll
    for (int i = 0; i < 8; i++)
#pragma unroll
        for (int j = 0; j < 8; j++) acc[i][j] = 0.0f;

#pragma unroll 4
    for (int k = 0; k < 64; k++) {
        float4 a0 = *(float4*)&sInT[k*260 + rg];
        float4 a1 = *(float4*)&sInT[k*260 + rg + 4];
        float4 w0 = *(float4*)&sW[k*68 + cg];
        float4 w1 = *(float4*)&sW[k*68 + cg + 4];
        float av[8] = {a0.x,a0.y,a0.z,a0.w,a1.x,a1.y,a1.z,a1.w};
        float wv[8] = {w0.x,w0.y,w0.z,w0.w,w1.x,w1.y,w1.z,w1.w};
#pragma unroll
        for (int i = 0; i < 8; i++)
#pragma unroll
            for (int j = 0; j < 8; j++)
                acc[i][j] = fmaf(av[i], wv[j], acc[i][j]);
    }

    float bb[8];
#pragma unroll
    for (int j = 0; j < 8; j++) bb[j] = sB[cg + j];
#pragma unroll
    for (int i = 0; i < 8; i++) {
        long p = (long)blockIdx.x*256 + rg + i;
        __half2 o[4];
#pragma unroll
        for (int j = 0; j < 4; j++) {
            float v0 = fmaxf(acc[i][2*j]   + bb[2*j],   0.f);
            float v1 = fmaxf(acc[i][2*j+1] + bb[2*j+1], 0.f);
            o[j] = __floats2half2_rn(v0, v1);
        }
        *reinterpret_cast<uint4*>(g_h1 + p*64 + cg) = *reinterpret_cast<uint4*>(o);
    }
}

// K1h2: gathered GEMM over edge rows, fp32 output.
__global__ void __launch_bounds__(256) k1h2(const float* __restrict__ Tprev,
                                            const float* __restrict__ Wt,
                                            const float* __restrict__ bt,
                                            int useNorm) {
    __shared__ float sIn[64][68];
    __shared__ float sW[64][64];
    __shared__ float sB[64];
    __shared__ int sP[64];
    int t = threadIdx.x;
    int np = g_npairs;
    for (int i = t; i < 4096; i += 256) sW[i >> 6][i & 63] = Wt[i];
    if (t < 64) {
        sB[t] = bt[t];
        int r = blockIdx.x * 64 + t;
        sP[t] = (r < np) ? g_pairs[r] : -1;
    }
    __syncthreads();
    for (int i = t; i < 1024; i += 256) {
        int r = i >> 4, j = (i & 15) << 2;
        int p = sP[r];
        float4 v = make_float4(0.f, 0.f, 0.f, 0.f);
        if (p >= 0) {
            v = *(const float4*)(Tprev + (long)p*64 + j);
            if (useNorm) {
                int bb = p / NPAIR;
                float4 sc = *(const float4*)(g_scale + bb*64 + j);
                float4 sh = *(const float4*)(g_shift + bb*64 + j);
                v.x = fmaxf(fmaf(v.x, sc.x, sh.x), 0.0f);
                v.y = fmaxf(fmaf(v.y, sc.y, sh.y), 0.0f);
                v.z = fmaxf(fmaf(v.z, sc.z, sh.z), 0.0f);
                v.w = fmaxf(fmaf(v.w, sc.w, sh.w), 0.0f);
            }
        }
        sIn[r][j] = v.x; sIn[r][j+1] = v.y; sIn[r][j+2] = v.z; sIn[r][j+3] = v.w;
    }
    __syncthreads();

    int cg = (t & 15) * 4, rg = (t >> 4) * 4;
    float acc[4][4];
#pragma unroll
    for (int i = 0; i < 4; i++)
#pragma unroll
        for (int j = 0; j < 4; j++) acc[i][j] = 0.0f;
#pragma unroll 16
    for (int k = 0; k < 64; k++) {
        float4 w = *(float4*)&sW[k][cg];
#pragma unroll
        for (int i = 0; i < 4; i++) {
            float a = sIn[rg + i][k];
            acc[i][0] = fmaf(a, w.x, acc[i][0]);
            acc[i][1] = fmaf(a, w.y, acc[i][1]);
            acc[i][2] = fmaf(a, w.z, acc[i][2]);
            acc[i][3] = fmaf(a, w.w, acc[i][3]);
        }
    }
    float4 bb = *(float4*)&sB[cg];
#pragma unroll
    for (int i = 0; i < 4; i++) {
        int p = sP[rg + i];
        if (p >= 0) {
            float4 o;
            o.x = fmaxf(acc[i][0] + bb.x, 0.0f);
            o.y = fmaxf(acc[i][1] + bb.y, 0.0f);
            o.z = fmaxf(acc[i][2] + bb.z, 0.0f);
            o.w = fmaxf(acc[i][3] + bb.w, 0.0f);
            *(float4*)(g_h2 + (long)p*64 + cg) = o;
        }
    }
}

// ---------------------------------------------------------------------------
// K2 sparse: M[b,u,v,d] = sum_{w in N(v)} h1[b,u,w,d] * h2[b,w,v,d]
// h1 fp16 (L2-hot gathers), h2 fp32 staged in smem, fp32 accumulation.
__global__ void __launch_bounds__(256) k2_sparse() {
    __shared__ int snbr[96];
    __shared__ float sh2[96*64];
    int t = threadIdx.x;
    int b = blockIdx.x / NN, v = blockIdx.x % NN;
    int deg = g_deg[b*NN + v];
    if (t < 96) snbr[t] = (t < deg) ? g_nbr[(b*NN + v)*NN + t] : 0;
    __syncthreads();
    for (int q = t; q < deg*16; q += 256) {
        int s = q >> 4, j = (q & 15) << 2;
        int w = snbr[s];
        *(float4*)&sh2[s*64 + j] =
            *(const float4*)(g_h2 + ((long)(b*NPAIR + w*NN + v) << 6) + j);
    }
    __syncthreads();

    int d0 = (t & 15) * 4, ug = t >> 4;      // ug 0..15, each owns 6 u's
    float4 acc[6];
#pragma unroll
    for (int i = 0; i < 6; i++) acc[i] = make_float4(0.f,0.f,0.f,0.f);

    const __half* h1b = g_h1 + ((long)b*NPAIR)*64 + (long)ug*6*6144 + d0;
    for (int s = 0; s < deg; s++) {
        int w = snbr[s];
        float4 h2v = *(float4*)&sh2[s*64 + d0];
        const __half* p0 = h1b + (long)w*64;
#pragma unroll
        for (int i = 0; i < 6; i++) {
            uint2 au = *reinterpret_cast<const uint2*>(p0 + (long)i*6144);
            float2 a0 = __half22float2(*reinterpret_cast<__half2*>(&au.x));
            float2 a1 = __half22float2(*reinterpret_cast<__half2*>(&au.y));
            acc[i].x = fmaf(a0.x, h2v.x, acc[i].x);
            acc[i].y = fmaf(a0.y, h2v.y, acc[i].y);
            acc[i].z = fmaf(a1.x, h2v.z, acc[i].z);
            acc[i].w = fmaf(a1.y, h2v.w, acc[i].w);
        }
    }
    float* Mb = g_M + ((long)(b*NPAIR + v))*64 + (long)ug*6*6144 + d0;
#pragma unroll
    for (int i = 0; i < 6; i++)
        *(float4*)(Mb + (long)i*6144) = acc[i];
}

// ---------------------------------------------------------------------------
// K3: Tcur = relu_norm(Tprev) + M@Wm + bm ; per-(b,d) stats. 256x64 tile, 8x8.
__global__ void __launch_bounds__(256) k3_update(const float* __restrict__ Tprev,
                                                 const float* __restrict__ Wm,
                                                 const float* __restrict__ bm,
                                                 int useNorm,
                                                 float* __restrict__ Tcur) {
    extern __shared__ float sm[];
    float* sInT = sm;
    float* sW   = sm + SM_INT;
    float* sB   = sW + SM_W;
    float* sSum = sB + 64;
    float* sSq  = sSum + 64;
    int t = threadIdx.x;
    int b = blockIdx.x / 36;
    long base = (long)blockIdx.x * 256 * 64;

    for (int i = t; i < 4096; i += 256) sW[(i >> 6)*68 + (i & 63)] = Wm[i];
    if (t < 64) { sB[t] = bm[t]; sSum[t] = 0.f; sSq[t] = 0.f; }

    int d  = t & 63;
    int r0 = (t >> 6) * 4;
#pragma unroll
    for (int it = 0; it < 16; it++) {
        int r = it*16 + r0;
#pragma unroll
        for (int q = 0; q < 4; q++)
            sInT[d*260 + r + q] = g_M[base + (long)(r + q)*64 + d];
    }
    __syncthreads();

    int cg = (t & 7) * 8;
    int rg = (t >> 3) * 8;
    float acc[8][8];
#pragma unroll
    for (int i = 0; i < 8; i++)
#pragma unroll
        for (int j = 0; j < 8; j++) acc[i][j] = 0.0f;

#pragma unroll 4
    for (int k = 0; k < 64; k++) {
        float4 a0 = *(float4*)&sInT[k*260 + rg];
        float4 a1 = *(float4*)&sInT[k*260 + rg + 4];
        float4 w0 = *(float4*)&sW[k*68 + cg];
        float4 w1 = *(float4*)&sW[k*68 + cg + 4];
        float av[8] = {a0.x,a0.y,a0.z,a0.w,a1.x,a1.y,a1.z,a1.w};
        float wv[8] = {w0.x,w0.y,w0.z,w0.w,w1.x,w1.y,w1.z,w1.w};
#pragma unroll
        for (int i = 0; i < 8; i++)
#pragma unroll
            for (int j = 0; j < 8; j++)
                acc[i][j] = fmaf(av[i], wv[j], acc[i][j]);
    }

    float bb[8], scn[8], shn[8];
#pragma unroll
    for (int j = 0; j < 8; j++) {
        bb[j] = sB[cg + j];
        scn[j] = useNorm ? g_scale[b*64 + cg + j] : 1.f;
        shn[j] = useNorm ? g_shift[b*64 + cg + j] : 0.f;
    }
    float cs[8], cq[8];
#pragma unroll
    for (int j = 0; j < 8; j++) { cs[j] = 0.f; cq[j] = 0.f; }

#pragma unroll
    for (int i = 0; i < 8; i++) {
        long p = (long)blockIdx.x*256 + rg + i;
        float4 wa = *(const float4*)(Tprev + p*64 + cg);
        float4 wb = *(const float4*)(Tprev + p*64 + cg + 4);
        float wv[8] = {wa.x,wa.y,wa.z,wa.w,wb.x,wb.y,wb.z,wb.w};
        float o[8];
#pragma unroll
        for (int j = 0; j < 8; j++) {
            float r = useNorm ? fmaxf(fmaf(wv[j], scn[j], shn[j]), 0.f) : wv[j];
            o[j] = acc[i][j] + bb[j] + r;
            cs[j] += o[j];
            cq[j] += o[j]*o[j];
        }
        *(float4*)(Tcur + p*64 + cg)     = make_float4(o[0],o[1],o[2],o[3]);
        *(float4*)(Tcur + p*64 + cg + 4) = make_float4(o[4],o[5],o[6],o[7]);
    }
    // reduce the 4 lanes (t, t^8, t^16, t^24) sharing cg
#pragma unroll
    for (int j = 0; j < 8; j++) {
        cs[j] += __shfl_xor_sync(0xffffffffu, cs[j], 8);
        cs[j] += __shfl_xor_sync(0xffffffffu, cs[j], 16);
        cq[j] += __shfl_xor_sync(0xffffffffu, cq[j], 8);
        cq[j] += __shfl_xor_sync(0xffffffffu, cq[j], 16);
    }
    if ((t & 24) == 0) {
#pragma unroll
        for (int j = 0; j < 8; j++) {
            atomicAdd(&sSum[cg + j], cs[j]);
            atomicAdd(&sSq [cg + j], cq[j]);
        }
    }
    __syncthreads();
    if (t < 64) {
        atomicAdd(&g_sum[b*64 + t], sSum[t]);
        atomicAdd(&g_sq [b*64 + t], sSq[t]);
    }
}

// stats + zero for next layer
__global__ void k_stats(const float* __restrict__ gamma,
                        const float* __restrict__ beta) {
    int i = blockIdx.x * 256 + threadIdx.x;
    if (i >= BB*DD) return;
    int d = i & 63;
    float mu  = g_sum[i] * (1.0f / NPAIR);
    float var = g_sq[i]  * (1.0f / NPAIR) - mu*mu;
    float s   = gamma[d] * rsqrtf(var + 1e-5f);
    g_scale[i] = s;
    g_shift[i] = beta[d] - mu * s;
    g_sum[i] = 0.f;
    g_sq[i]  = 0.f;
}

__global__ void __launch_bounds__(256) k_pool(const float* __restrict__ T) {
    __shared__ float sp[64];
    int t = threadIdx.x;
    long q = (long)blockIdx.x * 256 + t;
    long idx = q * 4;
    int d0 = (int)(idx & 63);
    int p  = (int)(idx >> 6);
    int b  = p / NPAIR;
    float4 v  = *(const float4*)(T + idx);
    float4 sc = *(const float4*)(g_scale + b*64 + d0);
    float4 sh = *(const float4*)(g_shift + b*64 + d0);
    float4 o;
    o.x = fmaxf(fmaf(v.x, sc.x, sh.x), 0.0f);
    o.y = fmaxf(fmaf(v.y, sc.y, sh.y), 0.0f);
    o.z = fmaxf(fmaf(v.z, sc.z, sh.z), 0.0f);
    o.w = fmaxf(fmaf(v.w, sc.w, sh.w), 0.0f);
    if (t < 64) sp[t] = 0.0f;
    __syncthreads();
    atomicAdd(&sp[d0+0], o.x);
    atomicAdd(&sp[d0+1], o.y);
    atomicAdd(&sp[d0+2], o.z);
    atomicAdd(&sp[d0+3], o.w);
    __syncthreads();
    if (t < 64) atomicAdd(&g_pool[b*64 + t], sp[t]);
}

__global__ void k5_out(const float* __restrict__ pw,
                       const float* __restrict__ pb,
                       float* __restrict__ out) {
    int t = threadIdx.x;
    int b = t >> 5, lane = t & 31;
    float v = g_pool[b*64 + lane]      * pw[lane]
            + g_pool[b*64 + lane + 32] * pw[lane + 32];
#pragma unroll
    for (int o = 16; o > 0; o >>= 1) v += __shfl_down_sync(0xffffffffu, v, o);
    if (lane == 0) out[b] = v + pb[0];
}

// ---------------------------------------------------------------------------
extern "C" void kernel_launch(void* const* d_in, const int* in_sizes, int n_in,
                              void* d_out, int out_size) {
    (void)in_sizes; (void)n_in; (void)out_size;
    const int*   x    = (const int*)d_in[0];
    const int*   ei   = (const int*)d_in[1];
    const int*   ea   = (const int*)d_in[2];
    const float* nemb = (const float*)d_in[3];
    const float* eemb = (const float*)d_in[4];
    const float* W1   = (const float*)d_in[5];
    const float* b1   = (const float*)d_in[6];
    const float* W2   = (const float*)d_in[7];
    const float* b2   = (const float*)d_in[8];
    const float* Wm   = (const float*)d_in[9];
    const float* bm   = (const float*)d_in[10];
    const float* gam  = (const float*)d_in[11];
    const float* bet  = (const float*)d_in[12];
    const float* pw   = (const float*)d_in[13];
    const float* pb   = (const float*)d_in[14];
    float* out = (float*)d_out;

    float* gT0; cudaGetSymbolAddress((void**)&gT0, g_T0);
    float* gT1; cudaGetSymbolAddress((void**)&gT1, g_T1);

    const int SMEMB = SM_TOTF * 4;
    cudaFuncSetAttribute(k1h1, cudaFuncAttributeMaxDynamicSharedMemorySize, SMEMB);
    cudaFuncSetAttribute(k3_update, cudaFuncAttributeMaxDynamicSharedMemorySize, SMEMB);

    k_init_clear<<<1152, 256>>>();
    k_scatter<<<96, 256>>>(ei, ea);
    k_decode<<<1152, 256>>>();
    k_initW<<<18432, 256>>>(x, nemb, eemb);   // -> g_T1

    for (int l = 0; l < LL; l++) {
        float* Tprev = (l % 2 == 0) ? gT1 : gT0;
        float* Tcur  = (l % 2 == 0) ? gT0 : gT1;
        int useNorm  = (l > 0) ? 1 : 0;
        k1h1<<<1152, 256, SMEMB>>>(Tprev, W1 + l*4096, b1 + l*64, useNorm);
        k1h2<<<768, 256>>>(Tprev, W2 + l*4096, b2 + l*64, useNorm);
        k2_sparse<<<3072, 256>>>();
        k3_update<<<1152, 256, SMEMB>>>(Tprev, Wm + l*4096, bm + l*64, useNorm, Tcur);
        k_stats<<<8, 256>>>(gam + l*64, bet + l*64);
    }
    k_pool<<<18432, 256>>>(gT0);
    k5_out<<<1, 1024>>>(pw, pb, out);
}

// round 5
// speedup vs baseline: 2.3949x; 1.0264x over previous
#include <cuda_runtime.h>
#include <cuda_fp16.h>

#define BB    32
#define NN    96
#define DD    64
#define LL    5
#define NPAIR 9216            // N*N
#define PTOT  294912          // B*N*N
#define BEP   24576           // B*EP
#define EV    5
#define MAXPAIRS 49152

// ---- scratch (device globals; no allocation allowed) ----
__device__ __align__(16) float g_T0 [PTOT*DD];
__device__ __align__(16) float g_T1 [PTOT*DD];
__device__ __align__(16) __half g_h1[PTOT*DD];          // h1[b,u,w,d] fp16
__device__ __align__(16) float  g_h2[PTOT*DD];          // h2[b,w,v,d] fp32 (edge slots)
__device__ int   g_aux[PTOT];
__device__ int   g_A  [PTOT];
__device__ int   g_deg[BB*NN];
__device__ int   g_nbr[BB*NN*NN];
__device__ int   g_pairs[MAXPAIRS];
__device__ int   g_npairs;
__device__ float g_sum[BB*DD];
__device__ float g_sq [BB*DD];
__device__ float g_scale[BB*DD];
__device__ float g_shift[BB*DD];
__device__ float g_pool[BB*DD];

// smem layout for k1h1 (floats): sInT[64][260] | sW[64][68] | sB[64]
#define SM_INT   (64*260)
#define SM_W     (64*68)
#define SM_TOTF  (SM_INT + SM_W + 64)

// smem layout for fused k23 (floats)
#define K23_SH2   0                    // 96*64
#define K23_SM    6144                 // 64*97 = 6208, sM[d*97+u]
#define K23_SWM   (6144+6208)          // 12352, 64*68
#define K23_SBM   16704                // 64
#define K23_SSUM  16768                // 64
#define K23_SSQ   16832                // 64
#define K23_SNBR  16896                // 96 ints
#define K23_TOTF  (16896 + 96)

// ---------------------------------------------------------------------------
__global__ void k_init_clear() {
    int i = blockIdx.x * 256 + threadIdx.x;
    if (i < PTOT)   g_aux[i] = -1;
    if (i < BB*DD)  { g_pool[i] = 0.0f; g_sum[i] = 0.0f; g_sq[i] = 0.0f; }
    if (i < BB*NN)  g_deg[i] = 0;
    if (i == 0)     g_npairs = 0;
}

__global__ void k_scatter(const int* __restrict__ ei, const int* __restrict__ ea) {
    int e = blockIdx.x * 256 + threadIdx.x;
    if (e >= BEP) return;
    int a = ei[e];
    int bnode = ei[BEP + e];
    int g = a / NN, u = a % NN, v = bnode % NN;
    int lab = ea[e] & 7;
    atomicMax(&g_aux[g*NPAIR + u*NN + v], (e << 3) | lab);
    atomicMax(&g_aux[g*NPAIR + v*NN + u], ((e + BEP) << 3) | lab);
}

__global__ void k_decode() {
    int i = blockIdx.x * 256 + threadIdx.x;
    if (i >= PTOT) return;
    int av = g_aux[i];
    int a  = (av < 0) ? EV : (av & 7);
    g_A[i] = a;
    if (a != EV) {
        int b = i / NPAIR, r = i % NPAIR;
        int w = r / NN, v = r % NN;
        int slot = atomicAdd(&g_deg[b*NN + v], 1);
        g_nbr[(b*NN + v)*NN + slot] = w;
        int ps = atomicAdd(&g_npairs, 1);
        g_pairs[ps] = i;
    }
}

__global__ void k_initW(const int* __restrict__ x,
                        const float* __restrict__ nemb,
                        const float* __restrict__ eemb) {
    long q = (long)blockIdx.x * 256 + threadIdx.x;
    int p  = (int)(q >> 4);
    int d0 = ((int)q & 15) << 2;
    int b = p / NPAIR, r = p % NPAIR, u = r / NN, v = r % NN;
    int xu = x[b*NN + u], xv = x[b*NN + v], a = g_A[p];
    float4 hu = *(const float4*)(nemb + xu*DD + d0);
    float4 hv = *(const float4*)(nemb + xv*DD + d0);
    float4 he = *(const float4*)(eemb + a*DD + d0);
    float4 o;
    o.x = hu.x + hv.x + he.x;
    o.y = hu.y + hv.y + he.y;
    o.z = hu.z + hv.z + he.z;
    o.w = hu.w + hv.w + he.w;
    *(float4*)(g_T1 + (long)p*DD + d0) = o;
}

// ---------------------------------------------------------------------------
// K1h1: h1 = relu( relu_norm(Tprev) @ W1 + b1 ), output fp16.
__global__ void __launch_bounds__(256) k1h1(const float* __restrict__ Tprev,
                                            const float* __restrict__ Wt,
                                            const float* __restrict__ bt,
                                            int useNorm) {
    extern __shared__ float sm[];
    float* sInT = sm;
    float* sW   = sm + SM_INT;
    float* sB   = sW + SM_W;
    int t = threadIdx.x;
    int b = blockIdx.x / 36;
    long base = (long)blockIdx.x * 256 * 64;

    for (int i = t; i < 4096; i += 256) sW[(i >> 6)*68 + (i & 63)] = Wt[i];
    if (t < 64) sB[t] = bt[t];

    int d  = t & 63;
    int r0 = (t >> 6) * 4;
    float sc = 1.f, sh = 0.f;
    if (useNorm) { sc = g_scale[b*64 + d]; sh = g_shift[b*64 + d]; }
#pragma unroll
    for (int it = 0; it < 16; it++) {
        int r = it*16 + r0;
#pragma unroll
        for (int q = 0; q < 4; q++) {
            float v = Tprev[base + (long)(r + q)*64 + d];
            if (useNorm) v = fmaxf(fmaf(v, sc, sh), 0.f);
            sInT[d*260 + r + q] = v;
        }
    }
    __syncthreads();

    int cg = (t & 7) * 8;
    int rg = (t >> 3) * 8;
    float acc[8][8];
#pragma unroll
    for (int i = 0; i < 8; i++)
#pragma unroll
        for (int j = 0; j < 8; j++) acc[i][j] = 0.0f;

#pragma unroll 4
    for (int k = 0; k < 64; k++) {
        float4 a0 = *(float4*)&sInT[k*260 + rg];
        float4 a1 = *(float4*)&sInT[k*260 + rg + 4];
        float4 w0 = *(float4*)&sW[k*68 + cg];
        float4 w1 = *(float4*)&sW[k*68 + cg + 4];
        float av[8] = {a0.x,a0.y,a0.z,a0.w,a1.x,a1.y,a1.z,a1.w};
        float wv[8] = {w0.x,w0.y,w0.z,w0.w,w1.x,w1.y,w1.z,w1.w};
#pragma unroll
        for (int i = 0; i < 8; i++)
#pragma unroll
            for (int j = 0; j < 8; j++)
                acc[i][j] = fmaf(av[i], wv[j], acc[i][j]);
    }

    float bb[8];
#pragma unroll
    for (int j = 0; j < 8; j++) bb[j] = sB[cg + j];
#pragma unroll
    for (int i = 0; i < 8; i++) {
        long p = (long)blockIdx.x*256 + rg + i;
        __half2 o[4];
#pragma unroll
        for (int j = 0; j < 4; j++) {
            float v0 = fmaxf(acc[i][2*j]   + bb[2*j],   0.f);
            float v1 = fmaxf(acc[i][2*j+1] + bb[2*j+1], 0.f);
            o[j] = __floats2half2_rn(v0, v1);
        }
        *reinterpret_cast<uint4*>(g_h1 + p*64 + cg) = *reinterpret_cast<uint4*>(o);
    }
}

// K1h2: gathered GEMM over edge rows, fp32 output.
__global__ void __launch_bounds__(256) k1h2(const float* __restrict__ Tprev,
                                            const float* __restrict__ Wt,
                                            const float* __restrict__ bt,
                                            int useNorm) {
    __shared__ float sIn[64][68];
    __shared__ float sW[64][64];
    __shared__ float sB[64];
    __shared__ int sP[64];
    int t = threadIdx.x;
    int np = g_npairs;
    for (int i = t; i < 4096; i += 256) sW[i >> 6][i & 63] = Wt[i];
    if (t < 64) {
        sB[t] = bt[t];
        int r = blockIdx.x * 64 + t;
        sP[t] = (r < np) ? g_pairs[r] : -1;
    }
    __syncthreads();
    for (int i = t; i < 1024; i += 256) {
        int r = i >> 4, j = (i & 15) << 2;
        int p = sP[r];
        float4 v = make_float4(0.f, 0.f, 0.f, 0.f);
        if (p >= 0) {
            v = *(const float4*)(Tprev + (long)p*64 + j);
            if (useNorm) {
                int bb = p / NPAIR;
                float4 sc = *(const float4*)(g_scale + bb*64 + j);
                float4 sh = *(const float4*)(g_shift + bb*64 + j);
                v.x = fmaxf(fmaf(v.x, sc.x, sh.x), 0.0f);
                v.y = fmaxf(fmaf(v.y, sc.y, sh.y), 0.0f);
                v.z = fmaxf(fmaf(v.z, sc.z, sh.z), 0.0f);
                v.w = fmaxf(fmaf(v.w, sc.w, sh.w), 0.0f);
            }
        }
        sIn[r][j] = v.x; sIn[r][j+1] = v.y; sIn[r][j+2] = v.z; sIn[r][j+3] = v.w;
    }
    __syncthreads();

    int cg = (t & 15) * 4, rg = (t >> 4) * 4;
    float acc[4][4];
#pragma unroll
    for (int i = 0; i < 4; i++)
#pragma unroll
        for (int j = 0; j < 4; j++) acc[i][j] = 0.0f;
#pragma unroll 16
    for (int k = 0; k < 64; k++) {
        float4 w = *(float4*)&sW[k][cg];
#pragma unroll
        for (int i = 0; i < 4; i++) {
            float a = sIn[rg + i][k];
            acc[i][0] = fmaf(a, w.x, acc[i][0]);
            acc[i][1] = fmaf(a, w.y, acc[i][1]);
            acc[i][2] = fmaf(a, w.z, acc[i][2]);
            acc[i][3] = fmaf(a, w.w, acc[i][3]);
        }
    }
    float4 bb = *(float4*)&sB[cg];
#pragma unroll
    for (int i = 0; i < 4; i++) {
        int p = sP[rg + i];
        if (p >= 0) {
            float4 o;
            o.x = fmaxf(acc[i][0] + bb.x, 0.0f);
            o.y = fmaxf(acc[i][1] + bb.y, 0.0f);
            o.z = fmaxf(acc[i][2] + bb.z, 0.0f);
            o.w = fmaxf(acc[i][3] + bb.w, 0.0f);
            *(float4*)(g_h2 + (long)p*64 + cg) = o;
        }
    }
}

// ---------------------------------------------------------------------------
// Fused K2+K3: per block (b,v):
//   M[u,d] = sum_{w in N(v)} h1[b,u,w,d] * h2[b,w,v,d]    (regs -> smem)
//   O[u,:] = relu_norm(Tprev[b,u,v,:]) + M[u,:]@Wm + bm   (GEMM from smem)
//   Tcur rows + per-(b,d) stats.
__global__ void __launch_bounds__(256) k23(const float* __restrict__ Tprev,
                                           const float* __restrict__ Wm,
                                           const float* __restrict__ bm,
                                           int useNorm,
                                           float* __restrict__ Tcur) {
    extern __shared__ float sm[];
    float* sh2  = sm + K23_SH2;
    float* sM   = sm + K23_SM;     // sM[d*97 + u]
    float* sWm  = sm + K23_SWM;    // sWm[d*68 + j]
    float* sBm  = sm + K23_SBM;
    float* sSum = sm + K23_SSUM;
    float* sSq  = sm + K23_SSQ;
    int*   snbr = (int*)(sm + K23_SNBR);

    int t = threadIdx.x;
    int b = blockIdx.x / NN, v = blockIdx.x % NN;
    int deg = g_deg[b*NN + v];

    for (int i = t; i < 4096; i += 256) sWm[(i >> 6)*68 + (i & 63)] = Wm[i];
    if (t < 64) { sBm[t] = bm[t]; sSum[t] = 0.f; sSq[t] = 0.f; }
    if (t < 96) snbr[t] = (t < deg) ? g_nbr[(b*NN + v)*NN + t] : 0;
    __syncthreads();

    // stage h2 neighbor rows
    for (int q = t; q < deg*16; q += 256) {
        int s = q >> 4, j = (q & 15) << 2;
        int w = snbr[s];
        *(float4*)&sh2[s*64 + j] =
            *(const float4*)(g_h2 + ((long)(b*NPAIR + w*NN + v) << 6) + j);
    }
    __syncthreads();

    // phase 2: sparse aggregation, thread = (d-slice, u-group)
    int d0 = (t & 15) * 4, ug = t >> 4;      // ug 0..15, 6 u's each
    float4 acc[6];
#pragma unroll
    for (int i = 0; i < 6; i++) acc[i] = make_float4(0.f,0.f,0.f,0.f);

    const __half* h1b = g_h1 + ((long)b*NPAIR)*64 + (long)ug*6*6144 + d0;
    for (int s = 0; s < deg; s++) {
        int w = snbr[s];
        float4 h2v = *(float4*)&sh2[s*64 + d0];
        const __half* p0 = h1b + (long)w*64;
#pragma unroll
        for (int i = 0; i < 6; i++) {
            uint2 au = *reinterpret_cast<const uint2*>(p0 + (long)i*6144);
            float2 a0 = __half22float2(*reinterpret_cast<__half2*>(&au.x));
            float2 a1 = __half22float2(*reinterpret_cast<__half2*>(&au.y));
            acc[i].x = fmaf(a0.x, h2v.x, acc[i].x);
            acc[i].y = fmaf(a0.y, h2v.y, acc[i].y);
            acc[i].z = fmaf(a1.x, h2v.z, acc[i].z);
            acc[i].w = fmaf(a1.y, h2v.w, acc[i].w);
        }
    }

    // phase 3: stage M transposed: sM[d][u]
#pragma unroll
    for (int i = 0; i < 6; i++) {
        int u = ug*6 + i;
        sM[(d0+0)*97 + u] = acc[i].x;
        sM[(d0+1)*97 + u] = acc[i].y;
        sM[(d0+2)*97 + u] = acc[i].z;
        sM[(d0+3)*97 + u] = acc[i].w;
    }
    __syncthreads();

    // phase 4: O = M @ Wm ; thread = (u-group of 6, j-quad)
    int u0 = (t >> 4) * 6, j0 = (t & 15) * 4;
    float a2[6][4];
#pragma unroll
    for (int i = 0; i < 6; i++)
#pragma unroll
        for (int j = 0; j < 4; j++) a2[i][j] = 0.f;

#pragma unroll 8
    for (int d = 0; d < 64; d++) {
        float4 w = *(float4*)&sWm[d*68 + j0];
        float a[6];
#pragma unroll
        for (int i = 0; i < 6; i++) a[i] = sM[d*97 + u0 + i];
#pragma unroll
        for (int i = 0; i < 6; i++) {
            a2[i][0] = fmaf(a[i], w.x, a2[i][0]);
            a2[i][1] = fmaf(a[i], w.y, a2[i][1]);
            a2[i][2] = fmaf(a[i], w.z, a2[i][2]);
            a2[i][3] = fmaf(a[i], w.w, a2[i][3]);
        }
    }

    // epilogue: residual + bias, stats, store
    float4 bb = *(float4*)&sBm[j0];
    float4 sc = make_float4(1.f,1.f,1.f,1.f), sh = make_float4(0.f,0.f,0.f,0.f);
    if (useNorm) {
        sc = *(const float4*)(g_scale + b*64 + j0);
        sh = *(const float4*)(g_shift + b*64 + j0);
    }
    float cs[4] = {0.f,0.f,0.f,0.f}, cq[4] = {0.f,0.f,0.f,0.f};
#pragma unroll
    for (int i = 0; i < 6; i++) {
        long p = (long)b*NPAIR + (long)(u0 + i)*NN + v;
        float4 wv = *(const float4*)(Tprev + p*64 + j0);
        if (useNorm) {
            wv.x = fmaxf(fmaf(wv.x, sc.x, sh.x), 0.f);
            wv.y = fmaxf(fmaf(wv.y, sc.y, sh.y), 0.f);
            wv.z = fmaxf(fmaf(wv.z, sc.z, sh.z), 0.f);
            wv.w = fmaxf(fmaf(wv.w, sc.w, sh.w), 0.f);
        }
        float4 o;
        o.x = a2[i][0] + bb.x + wv.x;
        o.y = a2[i][1] + bb.y + wv.y;
        o.z = a2[i][2] + bb.z + wv.z;
        o.w = a2[i][3] + bb.w + wv.w;
        *(float4*)(Tcur + p*64 + j0) = o;
        cs[0] += o.x; cq[0] += o.x*o.x;
        cs[1] += o.y; cq[1] += o.y*o.y;
        cs[2] += o.z; cq[2] += o.z*o.z;
        cs[3] += o.w; cq[3] += o.w*o.w;
    }
    // lanes l and l^16 share j0 (t&15 equal) -> pairwise reduce
#pragma unroll
    for (int q = 0; q < 4; q++) {
        cs[q] += __shfl_xor_sync(0xffffffffu, cs[q], 16);
        cq[q] += __shfl_xor_sync(0xffffffffu, cq[q], 16);
    }
    if ((t & 16) == 0) {
#pragma unroll
        for (int q = 0; q < 4; q++) {
            atomicAdd(&sSum[j0 + q], cs[q]);
            atomicAdd(&sSq [j0 + q], cq[q]);
        }
    }
    __syncthreads();
    if (t < 64) {
        atomicAdd(&g_sum[b*64 + t], sSum[t]);
        atomicAdd(&g_sq [b*64 + t], sSq[t]);
    }
}

// stats + zero for next layer
__global__ void k_stats(const float* __restrict__ gamma,
                        const float* __restrict__ beta) {
    int i = blockIdx.x * 256 + threadIdx.x;
    if (i >= BB*DD) return;
    int d = i & 63;
    float mu  = g_sum[i] * (1.0f / NPAIR);
    float var = g_sq[i]  * (1.0f / NPAIR) - mu*mu;
    float s   = gamma[d] * rsqrtf(var + 1e-5f);
    g_scale[i] = s;
    g_shift[i] = beta[d] - mu * s;
    g_sum[i] = 0.f;
    g_sq[i]  = 0.f;
}

__global__ void __launch_bounds__(256) k_pool(const float* __restrict__ T) {
    __shared__ float sp[64];
    int t = threadIdx.x;
    long q = (long)blockIdx.x * 256 + t;
    long idx = q * 4;
    int d0 = (int)(idx & 63);
    int p  = (int)(idx >> 6);
    int b  = p / NPAIR;
    float4 v  = *(const float4*)(T + idx);
    float4 sc = *(const float4*)(g_scale + b*64 + d0);
    float4 sh = *(const float4*)(g_shift + b*64 + d0);
    float4 o;
    o.x = fmaxf(fmaf(v.x, sc.x, sh.x), 0.0f);
    o.y = fmaxf(fmaf(v.y, sc.y, sh.y), 0.0f);
    o.z = fmaxf(fmaf(v.z, sc.z, sh.z), 0.0f);
    o.w = fmaxf(fmaf(v.w, sc.w, sh.w), 0.0f);
    if (t < 64) sp[t] = 0.0f;
    __syncthreads();
    atomicAdd(&sp[d0+0], o.x);
    atomicAdd(&sp[d0+1], o.y);
    atomicAdd(&sp[d0+2], o.z);
    atomicAdd(&sp[d0+3], o.w);
    __syncthreads();
    if (t < 64) atomicAdd(&g_pool[b*64 + t], sp[t]);
}

__global__ void k5_out(const float* __restrict__ pw,
                       const float* __restrict__ pb,
                       float* __restrict__ out) {
    int t = threadIdx.x;
    int b = t >> 5, lane = t & 31;
    float v = g_pool[b*64 + lane]      * pw[lane]
            + g_pool[b*64 + lane + 32] * pw[lane + 32];
#pragma unroll
    for (int o = 16; o > 0; o >>= 1) v += __shfl_down_sync(0xffffffffu, v, o);
    if (lane == 0) out[b] = v + pb[0];
}

// ---------------------------------------------------------------------------
extern "C" void kernel_launch(void* const* d_in, const int* in_sizes, int n_in,
                              void* d_out, int out_size) {
    (void)in_sizes; (void)n_in; (void)out_size;
    const int*   x    = (const int*)d_in[0];
    const int*   ei   = (const int*)d_in[1];
    const int*   ea   = (const int*)d_in[2];
    const float* nemb = (const float*)d_in[3];
    const float* eemb = (const float*)d_in[4];
    const float* W1   = (const float*)d_in[5];
    const float* b1   = (const float*)d_in[6];
    const float* W2   = (const float*)d_in[7];
    const float* b2   = (const float*)d_in[8];
    const float* Wm   = (const float*)d_in[9];
    const float* bm   = (const float*)d_in[10];
    const float* gam  = (const float*)d_in[11];
    const float* bet  = (const float*)d_in[12];
    const float* pw   = (const float*)d_in[13];
    const float* pb   = (const float*)d_in[14];
    float* out = (float*)d_out;

    float* gT0; cudaGetSymbolAddress((void**)&gT0, g_T0);
    float* gT1; cudaGetSymbolAddress((void**)&gT1, g_T1);

    const int SMEMB   = SM_TOTF * 4;
    const int SMEMB23 = K23_TOTF * 4;
    cudaFuncSetAttribute(k1h1, cudaFuncAttributeMaxDynamicSharedMemorySize, SMEMB);
    cudaFuncSetAttribute(k23,  cudaFuncAttributeMaxDynamicSharedMemorySize, SMEMB23);

    k_init_clear<<<1152, 256>>>();
    k_scatter<<<96, 256>>>(ei, ea);
    k_decode<<<1152, 256>>>();
    k_initW<<<18432, 256>>>(x, nemb, eemb);   // -> g_T1

    for (int l = 0; l < LL; l++) {
        float* Tprev = (l % 2 == 0) ? gT1 : gT0;
        float* Tcur  = (l % 2 == 0) ? gT0 : gT1;
        int useNorm  = (l > 0) ? 1 : 0;
        k1h1<<<1152, 256, SMEMB>>>(Tprev, W1 + l*4096, b1 + l*64, useNorm);
        k1h2<<<768, 256>>>(Tprev, W2 + l*4096, b2 + l*64, useNorm);
        k23<<<3072, 256, SMEMB23>>>(Tprev, Wm + l*4096, bm + l*64, useNorm, Tcur);
        k_stats<<<8, 256>>>(gam + l*64, bet + l*64);
    }
    k_pool<<<18432, 256>>>(gT0);
    k5_out<<<1, 1024>>>(pw, pb, out);
}

// round 8
// speedup vs baseline: 3.0949x; 1.2923x over previous
#include <cuda_runtime.h>
#include <cuda_fp16.h>
#include <cstdint>
#include <stdint.h>

#define BB    32
#define NN    96
#define DD    64
#define LL    5
#define NPAIR 9216            // N*N
#define PTOT  294912          // B*N*N
#define BEP   24576           // B*EP
#define EV    5
#define MAXPAIRS 49152

// ---- scratch (device globals; no allocation allowed) ----
__device__ __align__(16) float  g_T0 [PTOT*DD];
__device__ __align__(16) float  g_T1 [PTOT*DD];
__device__ __align__(16) __half g_h1 [PTOT*DD];   // h1[b,u,w,d] fp16
__device__ __align__(16) float  g_h2 [PTOT*DD];   // h2[b,w,v,d] fp32 (edge slots)
__device__ __align__(16) __half g_M16[PTOT*DD];   // aggregation output fp16
__device__ int   g_aux[PTOT];
__device__ int   g_A  [PTOT];
__device__ int   g_deg[BB*NN];
__device__ int   g_nbr[BB*NN*NN];
__device__ int   g_pairs[MAXPAIRS];
__device__ int   g_npairs;
__device__ float g_sum[BB*DD];
__device__ float g_sq [BB*DD];
__device__ float g_scale[BB*DD];
__device__ float g_shift[BB*DD];
__device__ float g_pool[BB*DD];

// smem byte layout for the mma GEMM kernels:
//   [0      : 34816)  sA (128x72 fp16, 18432B) reused as sO (128x68 fp32, 34816B)
//   [34816  : 44032)  sB (64x72 fp16)
//   [44032  : 44288)  bias (64 f32)
//   [44288  : 44544)  scale
//   [44544  : 44800)  shift
//   [44800  : 45056)  sSum (k3 only)
//   [45056  : 45312)  sSq  (k3 only)
#define SMEM_MMA 45312

__device__ __forceinline__ uint32_t smem_u32(const void* p) {
    uint32_t a;
    asm("{ .reg .u64 t; cvta.to.shared.u64 t, %1; cvt.u32.u64 %0, t; }"
        : "=r"(a) : "l"(p));
    return a;
}

__device__ __forceinline__ void ldmA(uint32_t a[4], uint32_t addr) {
    asm volatile("ldmatrix.sync.aligned.m8n8.x4.shared.b16 {%0,%1,%2,%3}, [%4];"
        : "=r"(a[0]), "=r"(a[1]), "=r"(a[2]), "=r"(a[3]) : "r"(addr));
}
__device__ __forceinline__ void ldmB(uint32_t b[2], uint32_t addr) {
    asm volatile("ldmatrix.sync.aligned.m8n8.x2.trans.shared.b16 {%0,%1}, [%2];"
        : "=r"(b[0]), "=r"(b[1]) : "r"(addr));
}
__device__ __forceinline__ void mma16816(float c[4], const uint32_t a[4],
                                         const uint32_t b[2]) {
    asm volatile(
        "mma.sync.aligned.m16n8k16.row.col.f32.f16.f16.f32 "
        "{%0,%1,%2,%3}, {%4,%5,%6,%7}, {%8,%9}, {%0,%1,%2,%3};"
        : "+f"(c[0]), "+f"(c[1]), "+f"(c[2]), "+f"(c[3])
        : "r"(a[0]), "r"(a[1]), "r"(a[2]), "r"(a[3]), "r"(b[0]), "r"(b[1]));
}

// ---------------------------------------------------------------------------
__global__ void k_init_clear() {
    int i = blockIdx.x * 256 + threadIdx.x;
    if (i < PTOT)   g_aux[i] = -1;
    if (i < BB*DD)  { g_pool[i] = 0.0f; g_sum[i] = 0.0f; g_sq[i] = 0.0f; }
    if (i < BB*NN)  g_deg[i] = 0;
    if (i == 0)     g_npairs = 0;
}

__global__ void k_scatter(const int* __restrict__ ei, const int* __restrict__ ea) {
    int e = blockIdx.x * 256 + threadIdx.x;
    if (e >= BEP) return;
    int a = ei[e];
    int bnode = ei[BEP + e];
    int g = a / NN, u = a % NN, v = bnode % NN;
    int lab = ea[e] & 7;
    atomicMax(&g_aux[g*NPAIR + u*NN + v], (e << 3) | lab);
    atomicMax(&g_aux[g*NPAIR + v*NN + u], ((e + BEP) << 3) | lab);
}

__global__ void k_decode() {
    int i = blockIdx.x * 256 + threadIdx.x;
    if (i >= PTOT) return;
    int av = g_aux[i];
    int a  = (av < 0) ? EV : (av & 7);
    g_A[i] = a;
    if (a != EV) {
        int b = i / NPAIR, r = i % NPAIR;
        int w = r / NN, v = r % NN;
        int slot = atomicAdd(&g_deg[b*NN + v], 1);
        g_nbr[(b*NN + v)*NN + slot] = w;
        int ps = atomicAdd(&g_npairs, 1);
        g_pairs[ps] = i;
    }
}

__global__ void k_initW(const int* __restrict__ x,
                        const float* __restrict__ nemb,
                        const float* __restrict__ eemb) {
    long q = (long)blockIdx.x * 256 + threadIdx.x;
    int p  = (int)(q >> 4);
    int d0 = ((int)q & 15) << 2;
    int b = p / NPAIR, r = p % NPAIR, u = r / NN, v = r % NN;
    int xu = x[b*NN + u], xv = x[b*NN + v], a = g_A[p];
    float4 hu = *(const float4*)(nemb + xu*DD + d0);
    float4 hv = *(const float4*)(nemb + xv*DD + d0);
    float4 he = *(const float4*)(eemb + a*DD + d0);
    float4 o;
    o.x = hu.x + hv.x + he.x;
    o.y = hu.y + hv.y + he.y;
    o.z = hu.z + hv.z + he.z;
    o.w = hu.w + hv.w + he.w;
    *(float4*)(g_T1 + (long)p*DD + d0) = o;
}

// ---------------------------------------------------------------------------
// k1h1_mma: h1 = relu( relu_norm(Tprev) @ W1 + b1 ), fp16 out, HMMA.
// grid PTOT/128 = 2304, 256 threads (8 warps x 16 rows).
__global__ void __launch_bounds__(256) k1h1_mma(const float* __restrict__ Tprev,
                                                const float* __restrict__ Wt,
                                                const float* __restrict__ bt,
                                                int useNorm) {
    extern __shared__ char smem[];
    __half* sA   = (__half*)smem;
    float*  sO   = (float*)smem;
    __half* sB   = (__half*)(smem + 34816);
    float* sBias = (float*)(smem + 44032);
    float* sSc   = (float*)(smem + 44288);
    float* sSh   = (float*)(smem + 44544);
    int t = threadIdx.x, w = t >> 5, l = t & 31;
    int b = blockIdx.x / 72;
    long tile0 = (long)blockIdx.x * 128;

    for (int i = t; i < 4096; i += 256) {
        int k = i >> 6, n = i & 63;
        sB[k*72 + n] = __float2half(Wt[i]);
    }
    if (t < 64) {
        sBias[t] = bt[t];
        sSc[t] = useNorm ? g_scale[b*64 + t] : 1.f;
        sSh[t] = useNorm ? g_shift[b*64 + t] : 0.f;
    }
    __syncthreads();

    // stage A: row r = t>>1, cols (t&1)*32..+32, fp32 -> norm -> fp16
    {
        int r = t >> 1, c0 = (t & 1) * 32;
        const float* src = Tprev + (tile0 + r) * 64 + c0;
        __half h[32];
#pragma unroll
        for (int j = 0; j < 32; j += 4) {
            float4 f = *(const float4*)(src + j);
            if (useNorm) {
                f.x = fmaxf(fmaf(f.x, sSc[c0+j+0], sSh[c0+j+0]), 0.f);
                f.y = fmaxf(fmaf(f.y, sSc[c0+j+1], sSh[c0+j+1]), 0.f);
                f.z = fmaxf(fmaf(f.z, sSc[c0+j+2], sSh[c0+j+2]), 0.f);
                f.w = fmaxf(fmaf(f.w, sSc[c0+j+3], sSh[c0+j+3]), 0.f);
            }
            h[j+0] = __float2half(f.x);
            h[j+1] = __float2half(f.y);
            h[j+2] = __float2half(f.z);
            h[j+3] = __float2half(f.w);
        }
        uint4* dst = (uint4*)(sA + r*72 + c0);
#pragma unroll
        for (int j = 0; j < 4; j++) dst[j] = ((uint4*)h)[j];
    }
    __syncthreads();

    uint32_t sAu = smem_u32(sA);
    uint32_t sBu = smem_u32(sB);
    int r0 = w * 16;
    uint32_t aF[4][4];
#pragma unroll
    for (int kk = 0; kk < 4; kk++)
        ldmA(aF[kk], sAu + (uint32_t)(((r0 + (l & 15))*72 + kk*16 + 8*(l >> 4)) << 1));

    float acc[8][4];
#pragma unroll
    for (int j = 0; j < 8; j++)
#pragma unroll
        for (int q = 0; q < 4; q++) acc[j][q] = 0.f;

#pragma unroll
    for (int j = 0; j < 8; j++) {
#pragma unroll
        for (int kk = 0; kk < 4; kk++) {
            uint32_t bF[2];
            ldmB(bF, sBu + (uint32_t)(((kk*16 + (l & 15))*72 + j*8) << 1));
            mma16816(acc[j], aF[kk], bF);
        }
    }
    __syncthreads();     // all warps done reading sA before sO overwrite
#pragma unroll
    for (int j = 0; j < 8; j++) {
        int row = r0 + (l >> 2);
        int col = j*8 + 2*(l & 3);
        *(float2*)&sO[row*68 + col]     = make_float2(acc[j][0], acc[j][1]);
        *(float2*)&sO[(row+8)*68 + col] = make_float2(acc[j][2], acc[j][3]);
    }
    __syncthreads();
    // epilogue: bias + relu -> fp16
    {
        int c2 = (t & 31) * 2, grp = t >> 5;
        float b0 = sBias[c2], b1 = sBias[c2+1];
#pragma unroll
        for (int i = 0; i < 16; i++) {
            int r = grp*16 + i;
            float2 f = *(float2*)&sO[r*68 + c2];
            __half2 o = __floats2half2_rn(fmaxf(f.x + b0, 0.f),
                                          fmaxf(f.y + b1, 0.f));
            *(__half2*)(g_h1 + (tile0 + r)*64 + c2) = o;
        }
    }
}

// ---------------------------------------------------------------------------
// K1h2: gathered GEMM over edge rows (fp32 math), fp32 output.
__global__ void __launch_bounds__(256) k1h2(const float* __restrict__ Tprev,
                                            const float* __restrict__ Wt,
                                            const float* __restrict__ bt,
                                            int useNorm) {
    __shared__ float sIn[64][68];
    __shared__ float sW[64][64];
    __shared__ float sB[64];
    __shared__ int sP[64];
    int t = threadIdx.x;
    int np = g_npairs;
    for (int i = t; i < 4096; i += 256) sW[i >> 6][i & 63] = Wt[i];
    if (t < 64) {
        sB[t] = bt[t];
        int r = blockIdx.x * 64 + t;
        sP[t] = (r < np) ? g_pairs[r] : -1;
    }
    __syncthreads();
    for (int i = t; i < 1024; i += 256) {
        int r = i >> 4, j = (i & 15) << 2;
        int p = sP[r];
        float4 v = make_float4(0.f, 0.f, 0.f, 0.f);
        if (p >= 0) {
            v = *(const float4*)(Tprev + (long)p*64 + j);
            if (useNorm) {
                int bb = p / NPAIR;
                float4 sc = *(const float4*)(g_scale + bb*64 + j);
                float4 sh = *(const float4*)(g_shift + bb*64 + j);
                v.x = fmaxf(fmaf(v.x, sc.x, sh.x), 0.0f);
                v.y = fmaxf(fmaf(v.y, sc.y, sh.y), 0.0f);
                v.z = fmaxf(fmaf(v.z, sc.z, sh.z), 0.0f);
                v.w = fmaxf(fmaf(v.w, sc.w, sh.w), 0.0f);
            }
        }
        sIn[r][j] = v.x; sIn[r][j+1] = v.y; sIn[r][j+2] = v.z; sIn[r][j+3] = v.w;
    }
    __syncthreads();

    int cg = (t & 15) * 4, rg = (t >> 4) * 4;
    float acc[4][4];
#pragma unroll
    for (int i = 0; i < 4; i++)
#pragma unroll
        for (int j = 0; j < 4; j++) acc[i][j] = 0.0f;
#pragma unroll 16
    for (int k = 0; k < 64; k++) {
        float4 w = *(float4*)&sW[k][cg];
#pragma unroll
        for (int i = 0; i < 4; i++) {
            float a = sIn[rg + i][k];
            acc[i][0] = fmaf(a, w.x, acc[i][0]);
            acc[i][1] = fmaf(a, w.y, acc[i][1]);
            acc[i][2] = fmaf(a, w.z, acc[i][2]);
            acc[i][3] = fmaf(a, w.w, acc[i][3]);
        }
    }
    float4 bb = *(float4*)&sB[cg];
#pragma unroll
    for (int i = 0; i < 4; i++) {
        int p = sP[rg + i];
        if (p >= 0) {
            float4 o;
            o.x = fmaxf(acc[i][0] + bb.x, 0.0f);
            o.y = fmaxf(acc[i][1] + bb.y, 0.0f);
            o.z = fmaxf(acc[i][2] + bb.z, 0.0f);
            o.w = fmaxf(acc[i][3] + bb.w, 0.0f);
            *(float4*)(g_h2 + (long)p*64 + cg) = o;
        }
    }
}

// ---------------------------------------------------------------------------
// K2 sparse: M16[b,u,v,d] = sum_{w in N(v)} h1[b,u,w,d] * h2[b,w,v,d] (fp16 out)
__global__ void __launch_bounds__(256) k2_sparse() {
    __shared__ int snbr[96];
    __shared__ float sh2[96*64];
    int t = threadIdx.x;
    int b = blockIdx.x / NN, v = blockIdx.x % NN;
    int deg = g_deg[b*NN + v];
    if (t < 96) snbr[t] = (t < deg) ? g_nbr[(b*NN + v)*NN + t] : 0;
    __syncthreads();
    for (int q = t; q < deg*16; q += 256) {
        int s = q >> 4, j = (q & 15) << 2;
        int w = snbr[s];
        *(float4*)&sh2[s*64 + j] =
            *(const float4*)(g_h2 + ((long)(b*NPAIR + w*NN + v) << 6) + j);
    }
    __syncthreads();

    int d0 = (t & 15) * 4, ug = t >> 4;
    float4 acc[6];
#pragma unroll
    for (int i = 0; i < 6; i++) acc[i] = make_float4(0.f,0.f,0.f,0.f);

    const __half* h1b = g_h1 + ((long)b*NPAIR)*64 + (long)ug*6*6144 + d0;
    for (int s = 0; s < deg; s++) {
        int w = snbr[s];
        float4 h2v = *(float4*)&sh2[s*64 + d0];
        const __half* p0 = h1b + (long)w*64;
#pragma unroll
        for (int i = 0; i < 6; i++) {
            uint2 au = *reinterpret_cast<const uint2*>(p0 + (long)i*6144);
            float2 a0 = __half22float2(*reinterpret_cast<__half2*>(&au.x));
            float2 a1 = __half22float2(*reinterpret_cast<__half2*>(&au.y));
            acc[i].x = fmaf(a0.x, h2v.x, acc[i].x);
            acc[i].y = fmaf(a0.y, h2v.y, acc[i].y);
            acc[i].z = fmaf(a1.x, h2v.z, acc[i].z);
            acc[i].w = fmaf(a1.y, h2v.w, acc[i].w);
        }
    }
    __half* Mb = g_M16 + ((long)(b*NPAIR + v))*64 + (long)ug*6*6144 + d0;
#pragma unroll
    for (int i = 0; i < 6; i++) {
        __half2 h0 = __floats2half2_rn(acc[i].x, acc[i].y);
        __half2 h1v = __floats2half2_rn(acc[i].z, acc[i].w);
        uint2 pk;
        pk.x = *reinterpret_cast<uint32_t*>(&h0);
        pk.y = *reinterpret_cast<uint32_t*>(&h1v);
        *(uint2*)(Mb + (long)i*6144) = pk;
    }
}

// ---------------------------------------------------------------------------
// k3_mma: Tcur = relu_norm(Tprev) + M16@Wm + bm, HMMA; per-(b,d) stats.
__global__ void __launch_bounds__(256) k3_mma(const float* __restrict__ Tprev,
                                              const float* __restrict__ Wm,
                                              const float* __restrict__ bm,
                                              int useNorm,
                                              float* __restrict__ Tcur) {
    extern __shared__ char smem[];
    __half* sA   = (__half*)smem;
    float*  sO   = (float*)smem;
    __half* sB   = (__half*)(smem + 34816);
    float* sBm   = (float*)(smem + 44032);
    float* sSc   = (float*)(smem + 44288);
    float* sSh   = (float*)(smem + 44544);
    float* sSum  = (float*)(smem + 44800);
    float* sSq   = (float*)(smem + 45056);
    int t = threadIdx.x, w = t >> 5, l = t & 31;
    int b = blockIdx.x / 72;
    long tile0 = (long)blockIdx.x * 128;

    for (int i = t; i < 4096; i += 256) {
        int k = i >> 6, n = i & 63;
        sB[k*72 + n] = __float2half(Wm[i]);
    }
    if (t < 64) {
        sBm[t] = bm[t];
        sSc[t] = useNorm ? g_scale[b*64 + t] : 1.f;
        sSh[t] = useNorm ? g_shift[b*64 + t] : 0.f;
        sSum[t] = 0.f;
        sSq[t] = 0.f;
    }
    // stage A = M16 rows (already fp16, straight copy)
    {
        int r = t >> 1, c0 = (t & 1) * 32;
        const uint4* src = (const uint4*)(g_M16 + (tile0 + r)*64 + c0);
        uint4* dst = (uint4*)(sA + r*72 + c0);
#pragma unroll
        for (int j = 0; j < 4; j++) dst[j] = src[j];
    }
    __syncthreads();

    uint32_t sAu = smem_u32(sA);
    uint32_t sBu = smem_u32(sB);
    int r0 = w * 16;
    uint32_t aF[4][4];
#pragma unroll
    for (int kk = 0; kk < 4; kk++)
        ldmA(aF[kk], sAu + (uint32_t)(((r0 + (l & 15))*72 + kk*16 + 8*(l >> 4)) << 1));

    float acc[8][4];
#pragma unroll
    for (int j = 0; j < 8; j++)
#pragma unroll
        for (int q = 0; q < 4; q++) acc[j][q] = 0.f;

#pragma unroll
    for (int j = 0; j < 8; j++) {
#pragma unroll
        for (int kk = 0; kk < 4; kk++) {
            uint32_t bF[2];
            ldmB(bF, sBu + (uint32_t)(((kk*16 + (l & 15))*72 + j*8) << 1));
            mma16816(acc[j], aF[kk], bF);
        }
    }
    __syncthreads();
#pragma unroll
    for (int j = 0; j < 8; j++) {
        int row = r0 + (l >> 2);
        int col = j*8 + 2*(l & 3);
        *(float2*)&sO[row*68 + col]     = make_float2(acc[j][0], acc[j][1]);
        *(float2*)&sO[(row+8)*68 + col] = make_float2(acc[j][2], acc[j][3]);
    }
    __syncthreads();
    // epilogue: bias + residual(norm) + store + stats
    {
        int c2 = (t & 31) * 2, grp = t >> 5;
        float b0 = sBm[c2], b1 = sBm[c2+1];
        float sc0 = sSc[c2], sc1 = sSc[c2+1];
        float sh0 = sSh[c2], sh1 = sSh[c2+1];
        float cs0 = 0.f, cs1 = 0.f, cq0 = 0.f, cq1 = 0.f;
#pragma unroll
        for (int i = 0; i < 16; i++) {
            int r = grp*16 + i;
            long p = tile0 + r;
            float2 m = *(float2*)&sO[r*68 + c2];
            float2 tv = *(const float2*)(Tprev + p*64 + c2);
            if (useNorm) {
                tv.x = fmaxf(fmaf(tv.x, sc0, sh0), 0.f);
                tv.y = fmaxf(fmaf(tv.y, sc1, sh1), 0.f);
            }
            float o0 = m.x + b0 + tv.x;
            float o1 = m.y + b1 + tv.y;
            *(float2*)(Tcur + p*64 + c2) = make_float2(o0, o1);
            cs0 += o0; cq0 += o0*o0;
            cs1 += o1; cq1 += o1*o1;
        }
        atomicAdd(&sSum[c2],   cs0);
        atomicAdd(&sSum[c2+1], cs1);
        atomicAdd(&sSq[c2],    cq0);
        atomicAdd(&sSq[c2+1],  cq1);
    }
    __syncthreads();
    if (t < 64) {
        atomicAdd(&g_sum[b*64 + t], sSum[t]);
        atomicAdd(&g_sq [b*64 + t], sSq[t]);
    }
}

// stats + zero for next layer
__global__ void k_stats(const float* __restrict__ gamma,
                        const float* __restrict__ beta) {
    int i = blockIdx.x * 256 + threadIdx.x;
    if (i >= BB*DD) return;
    int d = i & 63;
    float mu  = g_sum[i] * (1.0f / NPAIR);
    float var = g_sq[i]  * (1.0f / NPAIR) - mu*mu;
    float s   = gamma[d] * rsqrtf(var + 1e-5f);
    g_scale[i] = s;
    g_shift[i] = beta[d] - mu * s;
    g_sum[i] = 0.f;
    g_sq[i]  = 0.f;
}

__global__ void __launch_bounds__(256) k_pool(const float* __restrict__ T) {
    __shared__ float sp[64];
    int t = threadIdx.x;
    long q = (long)blockIdx.x * 256 + t;
    long idx = q * 4;
    int d0 = (int)(idx & 63);
    int p  = (int)(idx >> 6);
    int b  = p / NPAIR;
    float4 v  = *(const float4*)(T + idx);
    float4 sc = *(const float4*)(g_scale + b*64 + d0);
    float4 sh = *(const float4*)(g_shift + b*64 + d0);
    float4 o;
    o.x = fmaxf(fmaf(v.x, sc.x, sh.x), 0.0f);
    o.y = fmaxf(fmaf(v.y, sc.y, sh.y), 0.0f);
    o.z = fmaxf(fmaf(v.z, sc.z, sh.z), 0.0f);
    o.w = fmaxf(fmaf(v.w, sc.w, sh.w), 0.0f);
    if (t < 64) sp[t] = 0.0f;
    __syncthreads();
    atomicAdd(&sp[d0+0], o.x);
    atomicAdd(&sp[d0+1], o.y);
    atomicAdd(&sp[d0+2], o.z);
    atomicAdd(&sp[d0+3], o.w);
    __syncthreads();
    if (t < 64) atomicAdd(&g_pool[b*64 + t], sp[t]);
}

__global__ void k5_out(const float* __restrict__ pw,
                       const float* __restrict__ pb,
                       float* __restrict__ out) {
    int t = threadIdx.x;
    int b = t >> 5, lane = t & 31;
    float v = g_pool[b*64 + lane]      * pw[lane]
            + g_pool[b*64 + lane + 32] * pw[lane + 32];
#pragma unroll
    for (int o = 16; o > 0; o >>= 1) v += __shfl_down_sync(0xffffffffu, v, o);
    if (lane == 0) out[b] = v + pb[0];
}

// ---------------------------------------------------------------------------
extern "C" void kernel_launch(void* const* d_in, const int* in_sizes, int n_in,
                              void* d_out, int out_size) {
    (void)in_sizes; (void)n_in; (void)out_size;
    const int*   x    = (const int*)d_in[0];
    const int*   ei   = (const int*)d_in[1];
    const int*   ea   = (const int*)d_in[2];
    const float* nemb = (const float*)d_in[3];
    const float* eemb = (const float*)d_in[4];
    const float* W1   = (const float*)d_in[5];
    const float* b1   = (const float*)d_in[6];
    const float* W2   = (const float*)d_in[7];
    const float* b2   = (const float*)d_in[8];
    const float* Wm   = (const float*)d_in[9];
    const float* bm   = (const float*)d_in[10];
    const float* gam  = (const float*)d_in[11];
    const float* bet  = (const float*)d_in[12];
    const float* pw   = (const float*)d_in[13];
    const float* pb   = (const float*)d_in[14];
    float* out = (float*)d_out;

    float* gT0; cudaGetSymbolAddress((void**)&gT0, g_T0);
    float* gT1; cudaGetSymbolAddress((void**)&gT1, g_T1);

    cudaFuncSetAttribute(k1h1_mma, cudaFuncAttributeMaxDynamicSharedMemorySize, SMEM_MMA);
    cudaFuncSetAttribute(k3_mma,   cudaFuncAttributeMaxDynamicSharedMemorySize, SMEM_MMA);

    k_init_clear<<<1152, 256>>>();
    k_scatter<<<96, 256>>>(ei, ea);
    k_decode<<<1152, 256>>>();
    k_initW<<<18432, 256>>>(x, nemb, eemb);   // -> g_T1

    for (int l = 0; l < LL; l++) {
        float* Tprev = (l % 2 == 0) ? gT1 : gT0;
        float* Tcur  = (l % 2 == 0) ? gT0 : gT1;
        int useNorm  = (l > 0) ? 1 : 0;
        k1h1_mma<<<2304, 256, SMEM_MMA>>>(Tprev, W1 + l*4096, b1 + l*64, useNorm);
        k1h2<<<768, 256>>>(Tprev, W2 + l*4096, b2 + l*64, useNorm);
        k2_sparse<<<3072, 256>>>();
        k3_mma<<<2304, 256, SMEM_MMA>>>(Tprev, Wm + l*4096, bm + l*64, useNorm, Tcur);
        k_stats<<<8, 256>>>(gam + l*64, bet + l*64);
    }
    k_pool<<<18432, 256>>>(gT0);
    k5_out<<<1, 1024>>>(pw, pb, out);
}